// round 11
// baseline (speedup 1.0000x reference)
#include <cuda_runtime.h>
#include <cuda_bf16.h>
#include <math.h>
#include <stdint.h>

#define BB 8
#define CC 512
#define CQ 64
#define NN 4096   // H*W

typedef unsigned long long u64;
typedef unsigned int u32;

// ---------------- packed fp32x2 helpers ----------------
__device__ __forceinline__ u64 pack2(float lo, float hi) {
    u64 r; asm("mov.b64 %0, {%1, %2};" : "=l"(r) : "f"(lo), "f"(hi)); return r;
}
__device__ __forceinline__ void unpack2(u64 v, float& lo, float& hi) {
    asm("mov.b64 {%0, %1}, %2;" : "=f"(lo), "=f"(hi) : "l"(v));
}
__device__ __forceinline__ u64 ffma2(u64 a, u64 b, u64 c) {
    u64 d; asm("fma.rn.f32x2 %0, %1, %2, %3;" : "=l"(d) : "l"(a), "l"(b), "l"(c)); return d;
}

// bf16 pair pack: element order in memory = (lo_elem, hi_elem)
__device__ __forceinline__ u32 bf2(float lo, float hi) {
    u32 r; asm("cvt.rn.bf16x2.f32 %0, %1, %2;" : "=r"(r) : "f"(hi), "f"(lo)); return r;
}
__device__ __forceinline__ float bfround(float x) {
    return __bfloat162float(__float2bfloat16_rn(x));
}

// ---------------- cp.async helpers ----------------
__device__ __forceinline__ u32 smem_u32(const void* p) {
    u32 a;
    asm("{ .reg .u64 t; cvta.to.shared.u64 t, %1; cvt.u32.u64 %0, t; }" : "=r"(a) : "l"(p));
    return a;
}
__device__ __forceinline__ void cp16(u32 s, const void* g) {
    asm volatile("cp.async.cg.shared.global [%0], [%1], 16;" :: "r"(s), "l"(g));
}
#define CP_COMMIT()  asm volatile("cp.async.commit_group;" ::: "memory")
#define CP_WAIT(n)   asm volatile("cp.async.wait_group %0;" :: "n"(n) : "memory")

// ---------------- warp mma.sync bf16 ----------------
__device__ __forceinline__ void mma_bf16(float* c, const u32* a, u32 b0, u32 b1) {
    asm volatile(
        "mma.sync.aligned.m16n8k16.row.col.f32.bf16.bf16.f32 "
        "{%0,%1,%2,%3}, {%4,%5,%6,%7}, {%8,%9}, {%0,%1,%2,%3};"
        : "+f"(c[0]), "+f"(c[1]), "+f"(c[2]), "+f"(c[3])
        : "r"(a[0]), "r"(a[1]), "r"(a[2]), "r"(a[3]), "r"(b0), "r"(b1));
}

// ---------------- scratch (176 MB) ----------------
__device__ __nv_bfloat16 d_fhi[(size_t)BB * NN * CQ];     // f hi (b,i,d)   4 MB
__device__ __nv_bfloat16 d_flo[(size_t)BB * NN * CQ];     // f lo           4 MB
__device__ __nv_bfloat16 d_ghi[(size_t)BB * NN * CQ];     // g hi (b,j,d)   4 MB
__device__ __nv_bfloat16 d_glo[(size_t)BB * NN * CQ];     // g lo           4 MB
__device__ __nv_bfloat16 d_hThi[(size_t)BB * CC * NN];    // hT hi (b,c,i) 16 MB
__device__ __nv_bfloat16 d_hTlo[(size_t)BB * CC * NN];    // hT lo         16 MB
__device__ float d_S[(size_t)NN * NN];                    // S (one batch) 64 MB
__device__ __nv_bfloat16 d_Phi[(size_t)NN * NN];          // P hi          32 MB
__device__ __nv_bfloat16 d_Plo[(size_t)NN * NN];          // P lo          32 MB
__device__ float d_rsig[3];

// ---------------- 1) spectral sigma ----------------
__global__ void sigma_kernel(const float* __restrict__ Wf, const float* __restrict__ Wg,
                             const float* __restrict__ Wh, const float* __restrict__ uf,
                             const float* __restrict__ ug, const float* __restrict__ uh) {
    const int w = blockIdx.x;
    const float* W; const float* u; int M;
    if (w == 0)      { W = Wf; u = uf; M = CQ; }
    else if (w == 1) { W = Wg; u = ug; M = CQ; }
    else             { W = Wh; u = uh; M = CC; }
    const int K = CC;

    __shared__ float t[CC];
    __shared__ float red[CC];
    __shared__ float wsum[16];
    __shared__ float vnorm;
    const int tid = threadIdx.x;
    const int lane = tid & 31, warp = tid >> 5;

    float acc = 0.f;
#pragma unroll 8
    for (int m = 0; m < M; m++) acc += W[m * K + tid] * u[m];
    t[tid] = acc;
    red[tid] = acc * acc;
    __syncthreads();
    for (int s = 256; s > 0; s >>= 1) { if (tid < s) red[tid] += red[tid + s]; __syncthreads(); }
    if (tid == 0) vnorm = sqrtf(red[0]) + 1e-12f;
    __syncthreads();
    t[tid] *= (1.f / vnorm);
    __syncthreads();

    float local = 0.f;
    for (int m = warp; m < M; m += 16) {
        const float* Wr = W + (size_t)m * K;
        float a = 0.f;
#pragma unroll 4
        for (int k = lane; k < K; k += 32) a += Wr[k] * t[k];
#pragma unroll
        for (int o = 16; o > 0; o >>= 1) a += __shfl_xor_sync(0xFFFFFFFFu, a, o);
        local += a * a;
    }
    if (lane == 0) wsum[warp] = local;
    __syncthreads();
    if (tid == 0) {
        float nw2 = 0.f;
#pragma unroll
        for (int i = 0; i < 16; i++) nw2 += wsum[i];
        float nw = sqrtf(nw2);
        d_rsig[w] = (nw + 1e-12f) / nw2;   // 1/sigma
    }
}

// ---------------- 2) projections; all outputs bf16 hi/lo ----------------
__global__ void __launch_bounds__(256) proj_kernel(
    const float* __restrict__ x,
    const float* __restrict__ Wf, const float* __restrict__ bf,
    const float* __restrict__ Wg, const float* __restrict__ bg,
    const float* __restrict__ Wh, const float* __restrict__ bh) {
    const int K = CC;
    const int n0 = blockIdx.x * 64;
    const int o0 = blockIdx.y * 64;
    const int b  = blockIdx.z;

    const float* W; const float* bias; int seg, orow0;
    if (o0 < 64)       { seg = 0; W = Wf; bias = bf; orow0 = o0; }
    else if (o0 < 128) { seg = 1; W = Wg; bias = bg; orow0 = o0 - 64; }
    else               { seg = 2; W = Wh; bias = bh; orow0 = o0 - 128; }

    __shared__ float Ws[32][69];
    __shared__ float xs[32][68];

    const int tid = threadIdx.y * 16 + threadIdx.x;
    const int tx = threadIdx.x, ty = threadIdx.y;

    u64 accp[4][2];
#pragma unroll
    for (int i = 0; i < 4; i++) { accp[i][0] = 0ull; accp[i][1] = 0ull; }

    const size_t xbase = (size_t)b * CC * NN;

    for (int kc = 0; kc < K; kc += 32) {
#pragma unroll
        for (int r = 0; r < 8; r++) {
            int e = tid + 256 * r;
            int kk = e >> 6, nn = e & 63;
            xs[kk][nn] = x[xbase + (size_t)(kc + kk) * NN + n0 + nn];
        }
#pragma unroll
        for (int r = 0; r < 8; r++) {
            int e = tid + 256 * r;
            int kk = e & 31, oo = e >> 5;
            Ws[kk][oo] = W[(size_t)(orow0 + oo) * K + kc + kk];
        }
        __syncthreads();
#pragma unroll
        for (int kk = 0; kk < 32; kk++) {
            ulonglong2 bv = *(const ulonglong2*)&xs[kk][tx * 4];
#pragma unroll
            for (int i = 0; i < 4; i++) {
                float a = Ws[kk][ty * 4 + i];
                u64 A = pack2(a, a);
                accp[i][0] = ffma2(A, bv.x, accp[i][0]);
                accp[i][1] = ffma2(A, bv.y, accp[i][1]);
            }
        }
        __syncthreads();
    }

    const float rs = d_rsig[seg];
    const u64 rs2 = pack2(rs, rs);
    float vv[4][4];                          // [i(d)][j(n)]
#pragma unroll
    for (int i = 0; i < 4; i++) {
        const float bia = bias[orow0 + ty * 4 + i];
        const u64 b2 = pack2(bia, bia);
        u64 r0 = ffma2(accp[i][0], rs2, b2);
        u64 r1 = ffma2(accp[i][1], rs2, b2);
        unpack2(r0, vv[i][0], vv[i][1]);
        unpack2(r1, vv[i][2], vv[i][3]);
    }
    if (seg < 2) {
        __nv_bfloat16* Dhi = (seg == 0) ? d_fhi : d_ghi;
        __nv_bfloat16* Dlo = (seg == 0) ? d_flo : d_glo;
#pragma unroll
        for (int j = 0; j < 4; j++) {        // (b, n, d) layout: 4 consecutive d
            const int n = n0 + tx * 4 + j;
            float h0 = bfround(vv[0][j]), h1 = bfround(vv[1][j]);
            float h2 = bfround(vv[2][j]), h3 = bfround(vv[3][j]);
            uint2 ph; ph.x = bf2(h0, h1); ph.y = bf2(h2, h3);
            uint2 pl; pl.x = bf2(vv[0][j] - h0, vv[1][j] - h1);
            pl.y = bf2(vv[2][j] - h2, vv[3][j] - h3);
            const size_t base = ((size_t)b * NN + n) * CQ + orow0 + ty * 4;
            *(uint2*)&Dhi[base] = ph;
            *(uint2*)&Dlo[base] = pl;
        }
    } else {
#pragma unroll
        for (int i = 0; i < 4; i++) {        // hT (b, c, i): 4 consecutive n
            const int orow = orow0 + ty * 4 + i;
            float h0 = bfround(vv[i][0]), h1 = bfround(vv[i][1]);
            float h2 = bfround(vv[i][2]), h3 = bfround(vv[i][3]);
            uint2 ph; ph.x = bf2(h0, h1); ph.y = bf2(h2, h3);
            uint2 pl; pl.x = bf2(vv[i][0] - h0, vv[i][1] - h1);
            pl.y = bf2(vv[i][2] - h2, vv[i][3] - h3);
            const size_t base = ((size_t)b * CC + orow) * NN + n0 + tx * 4;
            *(uint2*)&d_hThi[base] = ph;
            *(uint2*)&d_hTlo[base] = pl;
        }
    }
}

// ---------------- 3) S = g f^T via mma (3-term bf16 split) ----------------
// CTA 128j x 128i, K=64 single shot. 8 warps: (wm 0..3)x(wn 0..1) -> 32j x 64i.
#define SST 72                         // padded row stride (bf16)
#define S_TILE (128 * SST)             // per array
#define S_SMEM (4 * S_TILE * 2)        // ghi, glo, fhi, flo  (73728 B)

extern __shared__ __nv_bfloat16 s_sm[];

__global__ void __launch_bounds__(256, 2) s_kernel(int b) {
    const int j0 = blockIdx.x * 128;
    const int i0 = blockIdx.y * 128;
    const int tid = threadIdx.x;
    const int lane = tid & 31, wid = tid >> 5;
    const int g = lane >> 2, t4 = lane & 3;
    const int jw = (wid >> 1) * 32;
    const int iw = (wid & 1) * 64;

    __nv_bfloat16* sghi = s_sm;
    __nv_bfloat16* sglo = s_sm + S_TILE;
    __nv_bfloat16* sfhi = s_sm + 2 * S_TILE;
    __nv_bfloat16* sflo = s_sm + 3 * S_TILE;

    // load tiles: 128 rows x 64 d (8 chunks of 16B) per array
    {
        const u32 sb = smem_u32(s_sm);
#pragma unroll
        for (int r = 0; r < 4; r++) {
            int e = tid + 256 * r;               // 1024 entries = 128 x 8
            int row = e >> 3, c16 = e & 7;
            u32 doff = row * (SST * 2) + c16 * 16;
            const size_t gsrc = ((size_t)b * NN + j0 + row) * CQ + c16 * 8;
            const size_t fsrc = ((size_t)b * NN + i0 + row) * CQ + c16 * 8;
            cp16(sb + doff, &d_ghi[gsrc]);
            cp16(sb + S_TILE * 2 + doff, &d_glo[gsrc]);
            cp16(sb + 2 * S_TILE * 2 + doff, &d_fhi[fsrc]);
            cp16(sb + 3 * S_TILE * 2 + doff, &d_flo[fsrc]);
        }
        CP_COMMIT();
        CP_WAIT(0);
    }
    __syncthreads();

    float acc[2][8][4];
#pragma unroll
    for (int mi = 0; mi < 2; mi++)
#pragma unroll
        for (int ni = 0; ni < 8; ni++)
#pragma unroll
            for (int q = 0; q < 4; q++) acc[mi][ni][q] = 0.f;

#pragma unroll
    for (int ks = 0; ks < 4; ks++) {
        const int cA = ks * 16 + 2 * t4;
        u32 ahi[2][4], alo[2][4];
#pragma unroll
        for (int mi = 0; mi < 2; mi++) {
            const int r0 = jw + mi * 16 + g;
            ahi[mi][0] = *(const u32*)&sghi[r0 * SST + cA];
            ahi[mi][1] = *(const u32*)&sghi[(r0 + 8) * SST + cA];
            ahi[mi][2] = *(const u32*)&sghi[r0 * SST + cA + 8];
            ahi[mi][3] = *(const u32*)&sghi[(r0 + 8) * SST + cA + 8];
            alo[mi][0] = *(const u32*)&sglo[r0 * SST + cA];
            alo[mi][1] = *(const u32*)&sglo[(r0 + 8) * SST + cA];
            alo[mi][2] = *(const u32*)&sglo[r0 * SST + cA + 8];
            alo[mi][3] = *(const u32*)&sglo[(r0 + 8) * SST + cA + 8];
        }
#pragma unroll
        for (int ni = 0; ni < 8; ni++) {
            const int nr = iw + ni * 8 + g;
            u32 bh0 = *(const u32*)&sfhi[nr * SST + cA];
            u32 bh1 = *(const u32*)&sfhi[nr * SST + cA + 8];
            u32 bl0 = *(const u32*)&sflo[nr * SST + cA];
            u32 bl1 = *(const u32*)&sflo[nr * SST + cA + 8];
#pragma unroll
            for (int mi = 0; mi < 2; mi++) {
                mma_bf16(acc[mi][ni], ahi[mi], bh0, bh1);
                mma_bf16(acc[mi][ni], ahi[mi], bl0, bl1);
                mma_bf16(acc[mi][ni], alo[mi], bh0, bh1);
            }
        }
    }

    // store S fp32
#pragma unroll
    for (int mi = 0; mi < 2; mi++) {
        const int m0 = j0 + jw + mi * 16 + g;
#pragma unroll
        for (int ni = 0; ni < 8; ni++) {
            const int ic = i0 + iw + ni * 8 + 2 * t4;
            *(u64*)&d_S[(size_t)m0 * NN + ic] = pack2(acc[mi][ni][0], acc[mi][ni][1]);
            *(u64*)&d_S[(size_t)(m0 + 8) * NN + ic] = pack2(acc[mi][ni][2], acc[mi][ni][3]);
        }
    }
}

// ---------------- 4) row softmax over i; emit P as bf16 hi/lo ----------------
__global__ void __launch_bounds__(256) softmax_kernel() {
    const int j = blockIdx.x;
    const float* row = d_S + (size_t)j * NN;
    const int tid = threadIdx.x;
    const int lane = tid & 31, warp = tid >> 5;
    __shared__ float red[8];
    __shared__ float bcast;

    float4 v[4];
#pragma unroll
    for (int r = 0; r < 4; r++) v[r] = *(const float4*)&row[(tid + 256 * r) * 4];

    float m = -INFINITY;
#pragma unroll
    for (int r = 0; r < 4; r++)
        m = fmaxf(m, fmaxf(fmaxf(v[r].x, v[r].y), fmaxf(v[r].z, v[r].w)));
#pragma unroll
    for (int o = 16; o > 0; o >>= 1) m = fmaxf(m, __shfl_xor_sync(0xFFFFFFFFu, m, o));
    if (lane == 0) red[warp] = m;
    __syncthreads();
    if (tid == 0) {
        float mm = red[0];
#pragma unroll
        for (int i = 1; i < 8; i++) mm = fmaxf(mm, red[i]);
        bcast = mm;
    }
    __syncthreads();
    const float M = bcast;

    float s = 0.f;
#pragma unroll
    for (int r = 0; r < 4; r++) {
        v[r].x = __expf(v[r].x - M); v[r].y = __expf(v[r].y - M);
        v[r].z = __expf(v[r].z - M); v[r].w = __expf(v[r].w - M);
        s += v[r].x + v[r].y + v[r].z + v[r].w;
    }
#pragma unroll
    for (int o = 16; o > 0; o >>= 1) s += __shfl_xor_sync(0xFFFFFFFFu, s, o);
    if (lane == 0) red[warp] = s;
    __syncthreads();
    if (tid == 0) {
        float ss = 0.f;
#pragma unroll
        for (int i = 0; i < 8; i++) ss += red[i];
        bcast = 1.f / ss;
    }
    __syncthreads();
    const float inv = bcast;
    const size_t ro = (size_t)j * NN;
#pragma unroll
    for (int r = 0; r < 4; r++) {
        float p0 = v[r].x * inv, p1 = v[r].y * inv, p2 = v[r].z * inv, p3 = v[r].w * inv;
        float h0 = bfround(p0), h1 = bfround(p1), h2 = bfround(p2), h3 = bfround(p3);
        uint2 ph; ph.x = bf2(h0, h1); ph.y = bf2(h2, h3);
        uint2 pl; pl.x = bf2(p0 - h0, p1 - h1); pl.y = bf2(p2 - h2, p3 - h3);
        const size_t idx = ro + (size_t)(tid + 256 * r) * 4;
        *(uint2*)&d_Phi[idx] = ph;
        *(uint2*)&d_Plo[idx] = pl;
    }
}

// ---------------- 5) PV via mma.sync (3-term split), retiled 32j x 256c ----------------
// Grid 128 x 2 = 256 CTAs. 8 warps, each 32j x 32c (cw = wid*32): mi 2 x ni 4.
// K = 4096 in chunks of 32, double-buffered cp.async.
#define TSTRIDE 40
#define ATILE_BF (32 * TSTRIDE)                 // 1280
#define BTILE_BF (256 * TSTRIDE)                // 10240
#define STAGE_BF (2 * ATILE_BF + 2 * BTILE_BF)  // 23040
#define PV_SMEM (2 * STAGE_BF * 2)              // 92160 B

extern __shared__ __nv_bfloat16 pv_sm[];

__device__ __forceinline__ void pv_load_stage(
    __nv_bfloat16* st, const __nv_bfloat16* Hhi, const __nv_bfloat16* Hlo,
    int j0, int c0, int kc, int tid) {
    const u32 sb = smem_u32(st);
    if (tid < 128) {                              // A: 32 rows x 4 chunks
        int row = tid >> 2, c16 = tid & 3;
        const size_t src = (size_t)(j0 + row) * NN + kc + c16 * 8;
        u32 dst = sb + row * (TSTRIDE * 2) + c16 * 16;
        cp16(dst, &d_Phi[src]);
        cp16(dst + ATILE_BF * 2, &d_Plo[src]);
    }
#pragma unroll
    for (int r = 0; r < 4; r++) {                 // B: 256 rows x 4 chunks
        int e = tid + 256 * r;
        int row = e >> 2, c16 = e & 3;
        const size_t src = (size_t)(c0 + row) * NN + kc + c16 * 8;
        u32 dst = sb + 2 * (ATILE_BF * 2) + row * (TSTRIDE * 2) + c16 * 16;
        cp16(dst, &Hhi[src]);
        cp16(dst + BTILE_BF * 2, &Hlo[src]);
    }
    CP_COMMIT();
}

__global__ void __launch_bounds__(256, 2) pv_kernel(
    int b, const float* __restrict__ x, const float* __restrict__ gamma,
    float* __restrict__ out) {
    const int j0 = blockIdx.x * 32;
    const int c0 = blockIdx.y * 256;
    const int tid = threadIdx.x;
    const int lane = tid & 31, wid = tid >> 5;
    const int g = lane >> 2, t4 = lane & 3;
    const int cw = wid * 32;                      // warp c offset

    const __nv_bfloat16* Hhi = d_hThi + (size_t)b * CC * NN;
    const __nv_bfloat16* Hlo = d_hTlo + (size_t)b * CC * NN;

    float acc[2][4][4];
#pragma unroll
    for (int mi = 0; mi < 2; mi++)
#pragma unroll
        for (int ni = 0; ni < 4; ni++)
#pragma unroll
            for (int q = 0; q < 4; q++) acc[mi][ni][q] = 0.f;

    pv_load_stage(pv_sm, Hhi, Hlo, j0, c0, 0, tid);

    for (int tch = 0; tch < 128; tch++) {
        if (tch + 1 < 128) {
            pv_load_stage(pv_sm + ((tch + 1) & 1) * STAGE_BF, Hhi, Hlo,
                          j0, c0, (tch + 1) * 32, tid);
            CP_WAIT(1);
        } else {
            CP_WAIT(0);
        }
        __syncthreads();

        const __nv_bfloat16* st = pv_sm + (tch & 1) * STAGE_BF;
        const __nv_bfloat16* sAhi = st;
        const __nv_bfloat16* sAlo = st + ATILE_BF;
        const __nv_bfloat16* sBhi = st + 2 * ATILE_BF;
        const __nv_bfloat16* sBlo = st + 2 * ATILE_BF + BTILE_BF;

#pragma unroll
        for (int s = 0; s < 2; s++) {
            const int cA = s * 16 + 2 * t4;
            u32 ahi[2][4], alo[2][4];
#pragma unroll
            for (int mi = 0; mi < 2; mi++) {
                const int r0 = mi * 16 + g;
                ahi[mi][0] = *(const u32*)&sAhi[r0 * TSTRIDE + cA];
                ahi[mi][1] = *(const u32*)&sAhi[(r0 + 8) * TSTRIDE + cA];
                ahi[mi][2] = *(const u32*)&sAhi[r0 * TSTRIDE + cA + 8];
                ahi[mi][3] = *(const u32*)&sAhi[(r0 + 8) * TSTRIDE + cA + 8];
                alo[mi][0] = *(const u32*)&sAlo[r0 * TSTRIDE + cA];
                alo[mi][1] = *(const u32*)&sAlo[(r0 + 8) * TSTRIDE + cA];
                alo[mi][2] = *(const u32*)&sAlo[r0 * TSTRIDE + cA + 8];
                alo[mi][3] = *(const u32*)&sAlo[(r0 + 8) * TSTRIDE + cA + 8];
            }
#pragma unroll
            for (int ni = 0; ni < 4; ni++) {
                const int nr = cw + ni * 8 + g;
                u32 bh0 = *(const u32*)&sBhi[nr * TSTRIDE + cA];
                u32 bh1 = *(const u32*)&sBhi[nr * TSTRIDE + cA + 8];
                u32 bl0 = *(const u32*)&sBlo[nr * TSTRIDE + cA];
                u32 bl1 = *(const u32*)&sBlo[nr * TSTRIDE + cA + 8];
#pragma unroll
                for (int mi = 0; mi < 2; mi++) {
                    mma_bf16(acc[mi][ni], ahi[mi], bh0, bh1);   // hi*hi
                    mma_bf16(acc[mi][ni], ahi[mi], bl0, bl1);   // hi*lo
                    mma_bf16(acc[mi][ni], alo[mi], bh0, bh1);   // lo*hi
                }
            }
        }
        __syncthreads();
    }

    // epilogue: y[b,c,j] = gamma * o + x
    const float gam = gamma[0];
    const size_t xb = (size_t)b * CC * NN;
#pragma unroll
    for (int mi = 0; mi < 2; mi++) {
        const int m0 = j0 + mi * 16 + g;
#pragma unroll
        for (int ni = 0; ni < 4; ni++) {
            const int n0 = c0 + cw + ni * 8 + 2 * t4;
            const size_t i00 = xb + (size_t)n0 * NN + m0;
            const size_t i01 = i00 + NN;
            out[i00]     = gam * acc[mi][ni][0] + x[i00];
            out[i01]     = gam * acc[mi][ni][1] + x[i01];
            out[i00 + 8] = gam * acc[mi][ni][2] + x[i00 + 8];
            out[i01 + 8] = gam * acc[mi][ni][3] + x[i01 + 8];
        }
    }
}

// ---------------- launch ----------------
extern "C" void kernel_launch(void* const* d_in, const int* in_sizes, int n_in,
                              void* d_out, int out_size) {
    (void)in_sizes; (void)n_in; (void)out_size;
    const float* x     = (const float*)d_in[0];
    const float* Wf    = (const float*)d_in[1];
    const float* bf    = (const float*)d_in[2];
    const float* Wg    = (const float*)d_in[3];
    const float* bg    = (const float*)d_in[4];
    const float* Wh    = (const float*)d_in[5];
    const float* bh    = (const float*)d_in[6];
    const float* gamma = (const float*)d_in[7];
    const float* uf    = (const float*)d_in[8];
    const float* ug    = (const float*)d_in[9];
    const float* uh    = (const float*)d_in[10];
    float* out = (float*)d_out;

    cudaFuncSetAttribute(s_kernel, cudaFuncAttributeMaxDynamicSharedMemorySize, S_SMEM);
    cudaFuncSetAttribute(pv_kernel, cudaFuncAttributeMaxDynamicSharedMemorySize, PV_SMEM);

    sigma_kernel<<<3, 512>>>(Wf, Wg, Wh, uf, ug, uh);
    proj_kernel<<<dim3(NN / 64, 10, BB), dim3(16, 16)>>>(x, Wf, bf, Wg, bg, Wh, bh);
    for (int b = 0; b < BB; b++) {
        s_kernel<<<dim3(NN / 128, NN / 128), 256, S_SMEM>>>(b);
        softmax_kernel<<<NN, 256>>>();
        pv_kernel<<<dim3(NN / 32, CC / 256), 256, PV_SMEM>>>(b, x, gamma, out);
    }
}

// round 12
// speedup vs baseline: 1.2301x; 1.2301x over previous
#include <cuda_runtime.h>
#include <cuda_bf16.h>
#include <math.h>
#include <stdint.h>

#define BB 8
#define CC 512
#define CQ 64
#define NN 4096   // H*W

typedef unsigned long long u64;
typedef unsigned int u32;

// ---------------- packed fp32x2 helpers ----------------
__device__ __forceinline__ u64 pack2(float lo, float hi) {
    u64 r; asm("mov.b64 %0, {%1, %2};" : "=l"(r) : "f"(lo), "f"(hi)); return r;
}
__device__ __forceinline__ void unpack2(u64 v, float& lo, float& hi) {
    asm("mov.b64 {%0, %1}, %2;" : "=f"(lo), "=f"(hi) : "l"(v));
}
__device__ __forceinline__ u64 ffma2(u64 a, u64 b, u64 c) {
    u64 d; asm("fma.rn.f32x2 %0, %1, %2, %3;" : "=l"(d) : "l"(a), "l"(b), "l"(c)); return d;
}

// bf16 pair pack: element order in memory = (lo_elem, hi_elem)
__device__ __forceinline__ u32 bf2(float lo, float hi) {
    u32 r; asm("cvt.rn.bf16x2.f32 %0, %1, %2;" : "=r"(r) : "f"(hi), "f"(lo)); return r;
}
__device__ __forceinline__ float bfround(float x) {
    return __bfloat162float(__float2bfloat16_rn(x));
}

// ---------------- cp.async / smem helpers ----------------
__device__ __forceinline__ u32 smem_u32(const void* p) {
    u32 a;
    asm("{ .reg .u64 t; cvta.to.shared.u64 t, %1; cvt.u32.u64 %0, t; }" : "=r"(a) : "l"(p));
    return a;
}
__device__ __forceinline__ void cp16(u32 s, const void* g) {
    asm volatile("cp.async.cg.shared.global [%0], [%1], 16;" :: "r"(s), "l"(g));
}
#define CP_COMMIT()  asm volatile("cp.async.commit_group;" ::: "memory")
#define CP_WAIT(n)   asm volatile("cp.async.wait_group %0;" :: "n"(n) : "memory")

// ---------------- warp mma.sync bf16 + ldmatrix ----------------
__device__ __forceinline__ void mma_bf16(float* c, const u32* a, u32 b0, u32 b1) {
    asm volatile(
        "mma.sync.aligned.m16n8k16.row.col.f32.bf16.bf16.f32 "
        "{%0,%1,%2,%3}, {%4,%5,%6,%7}, {%8,%9}, {%0,%1,%2,%3};"
        : "+f"(c[0]), "+f"(c[1]), "+f"(c[2]), "+f"(c[3])
        : "r"(a[0]), "r"(a[1]), "r"(a[2]), "r"(a[3]), "r"(b0), "r"(b1));
}
__device__ __forceinline__ void ldsm_x4(u32* r, u32 addr) {
    asm volatile("ldmatrix.sync.aligned.m8n8.x4.shared.b16 {%0,%1,%2,%3}, [%4];"
                 : "=r"(r[0]), "=r"(r[1]), "=r"(r[2]), "=r"(r[3]) : "r"(addr));
}

// ---------------- scratch (176 MB) ----------------
__device__ __nv_bfloat16 d_fhi[(size_t)BB * NN * CQ];     // f hi (b,i,d)   4 MB
__device__ __nv_bfloat16 d_flo[(size_t)BB * NN * CQ];     // f lo           4 MB
__device__ __nv_bfloat16 d_ghi[(size_t)BB * NN * CQ];     // g hi (b,j,d)   4 MB
__device__ __nv_bfloat16 d_glo[(size_t)BB * NN * CQ];     // g lo           4 MB
__device__ __nv_bfloat16 d_hThi[(size_t)BB * CC * NN];    // hT hi (b,c,i) 16 MB
__device__ __nv_bfloat16 d_hTlo[(size_t)BB * CC * NN];    // hT lo         16 MB
__device__ float d_S[(size_t)NN * NN];                    // S (one batch) 64 MB
__device__ __nv_bfloat16 d_Phi[(size_t)NN * NN];          // P hi          32 MB
__device__ __nv_bfloat16 d_Plo[(size_t)NN * NN];          // P lo          32 MB
__device__ float d_rsig[3];

// ---------------- 1) spectral sigma ----------------
__global__ void sigma_kernel(const float* __restrict__ Wf, const float* __restrict__ Wg,
                             const float* __restrict__ Wh, const float* __restrict__ uf,
                             const float* __restrict__ ug, const float* __restrict__ uh) {
    const int w = blockIdx.x;
    const float* W; const float* u; int M;
    if (w == 0)      { W = Wf; u = uf; M = CQ; }
    else if (w == 1) { W = Wg; u = ug; M = CQ; }
    else             { W = Wh; u = uh; M = CC; }
    const int K = CC;

    __shared__ float t[CC];
    __shared__ float red[CC];
    __shared__ float wsum[16];
    __shared__ float vnorm;
    const int tid = threadIdx.x;
    const int lane = tid & 31, warp = tid >> 5;

    float acc = 0.f;
#pragma unroll 8
    for (int m = 0; m < M; m++) acc += W[m * K + tid] * u[m];
    t[tid] = acc;
    red[tid] = acc * acc;
    __syncthreads();
    for (int s = 256; s > 0; s >>= 1) { if (tid < s) red[tid] += red[tid + s]; __syncthreads(); }
    if (tid == 0) vnorm = sqrtf(red[0]) + 1e-12f;
    __syncthreads();
    t[tid] *= (1.f / vnorm);
    __syncthreads();

    float local = 0.f;
    for (int m = warp; m < M; m += 16) {
        const float* Wr = W + (size_t)m * K;
        float a = 0.f;
#pragma unroll 4
        for (int k = lane; k < K; k += 32) a += Wr[k] * t[k];
#pragma unroll
        for (int o = 16; o > 0; o >>= 1) a += __shfl_xor_sync(0xFFFFFFFFu, a, o);
        local += a * a;
    }
    if (lane == 0) wsum[warp] = local;
    __syncthreads();
    if (tid == 0) {
        float nw2 = 0.f;
#pragma unroll
        for (int i = 0; i < 16; i++) nw2 += wsum[i];
        float nw = sqrtf(nw2);
        d_rsig[w] = (nw + 1e-12f) / nw2;   // 1/sigma
    }
}

// ---------------- 2) projections; all outputs bf16 hi/lo ----------------
__global__ void __launch_bounds__(256) proj_kernel(
    const float* __restrict__ x,
    const float* __restrict__ Wf, const float* __restrict__ bf,
    const float* __restrict__ Wg, const float* __restrict__ bg,
    const float* __restrict__ Wh, const float* __restrict__ bh) {
    const int K = CC;
    const int n0 = blockIdx.x * 64;
    const int o0 = blockIdx.y * 64;
    const int b  = blockIdx.z;

    const float* W; const float* bias; int seg, orow0;
    if (o0 < 64)       { seg = 0; W = Wf; bias = bf; orow0 = o0; }
    else if (o0 < 128) { seg = 1; W = Wg; bias = bg; orow0 = o0 - 64; }
    else               { seg = 2; W = Wh; bias = bh; orow0 = o0 - 128; }

    __shared__ float Ws[32][69];
    __shared__ float xs[32][68];

    const int tid = threadIdx.y * 16 + threadIdx.x;
    const int tx = threadIdx.x, ty = threadIdx.y;

    u64 accp[4][2];
#pragma unroll
    for (int i = 0; i < 4; i++) { accp[i][0] = 0ull; accp[i][1] = 0ull; }

    const size_t xbase = (size_t)b * CC * NN;

    for (int kc = 0; kc < K; kc += 32) {
#pragma unroll
        for (int r = 0; r < 8; r++) {
            int e = tid + 256 * r;
            int kk = e >> 6, nn = e & 63;
            xs[kk][nn] = x[xbase + (size_t)(kc + kk) * NN + n0 + nn];
        }
#pragma unroll
        for (int r = 0; r < 8; r++) {
            int e = tid + 256 * r;
            int kk = e & 31, oo = e >> 5;
            Ws[kk][oo] = W[(size_t)(orow0 + oo) * K + kc + kk];
        }
        __syncthreads();
#pragma unroll
        for (int kk = 0; kk < 32; kk++) {
            ulonglong2 bv = *(const ulonglong2*)&xs[kk][tx * 4];
#pragma unroll
            for (int i = 0; i < 4; i++) {
                float a = Ws[kk][ty * 4 + i];
                u64 A = pack2(a, a);
                accp[i][0] = ffma2(A, bv.x, accp[i][0]);
                accp[i][1] = ffma2(A, bv.y, accp[i][1]);
            }
        }
        __syncthreads();
    }

    const float rs = d_rsig[seg];
    const u64 rs2 = pack2(rs, rs);
    float vv[4][4];                          // [i(d)][j(n)]
#pragma unroll
    for (int i = 0; i < 4; i++) {
        const float bia = bias[orow0 + ty * 4 + i];
        const u64 b2 = pack2(bia, bia);
        u64 r0 = ffma2(accp[i][0], rs2, b2);
        u64 r1 = ffma2(accp[i][1], rs2, b2);
        unpack2(r0, vv[i][0], vv[i][1]);
        unpack2(r1, vv[i][2], vv[i][3]);
    }
    if (seg < 2) {
        __nv_bfloat16* Dhi = (seg == 0) ? d_fhi : d_ghi;
        __nv_bfloat16* Dlo = (seg == 0) ? d_flo : d_glo;
#pragma unroll
        for (int j = 0; j < 4; j++) {        // (b, n, d) layout: 4 consecutive d
            const int n = n0 + tx * 4 + j;
            float h0 = bfround(vv[0][j]), h1 = bfround(vv[1][j]);
            float h2 = bfround(vv[2][j]), h3 = bfround(vv[3][j]);
            uint2 ph; ph.x = bf2(h0, h1); ph.y = bf2(h2, h3);
            uint2 pl; pl.x = bf2(vv[0][j] - h0, vv[1][j] - h1);
            pl.y = bf2(vv[2][j] - h2, vv[3][j] - h3);
            const size_t base = ((size_t)b * NN + n) * CQ + orow0 + ty * 4;
            *(uint2*)&Dhi[base] = ph;
            *(uint2*)&Dlo[base] = pl;
        }
    } else {
#pragma unroll
        for (int i = 0; i < 4; i++) {        // hT (b, c, i): 4 consecutive n
            const int orow = orow0 + ty * 4 + i;
            float h0 = bfround(vv[i][0]), h1 = bfround(vv[i][1]);
            float h2 = bfround(vv[i][2]), h3 = bfround(vv[i][3]);
            uint2 ph; ph.x = bf2(h0, h1); ph.y = bf2(h2, h3);
            uint2 pl; pl.x = bf2(vv[i][0] - h0, vv[i][1] - h1);
            pl.y = bf2(vv[i][2] - h2, vv[i][3] - h3);
            const size_t base = ((size_t)b * CC + orow) * NN + n0 + tx * 4;
            *(uint2*)&d_hThi[base] = ph;
            *(uint2*)&d_hTlo[base] = pl;
        }
    }
}

// ---------------- 3) S = g f^T via mma (3-term bf16 split) ----------------
// CTA 128j x 128i, K=64 single shot. 8 warps: (wm 0..3)x(wn 0..1) -> 32j x 64i.
#define SST 72                         // padded row stride (bf16)
#define S_TILE (128 * SST)             // per array
#define S_SMEM (4 * S_TILE * 2)        // ghi, glo, fhi, flo  (73728 B)

extern __shared__ __nv_bfloat16 s_sm[];

__global__ void __launch_bounds__(256, 2) s_kernel(int b) {
    const int j0 = blockIdx.x * 128;
    const int i0 = blockIdx.y * 128;
    const int tid = threadIdx.x;
    const int lane = tid & 31, wid = tid >> 5;
    const int g = lane >> 2, t4 = lane & 3;
    const int jw = (wid >> 1) * 32;
    const int iw = (wid & 1) * 64;

    __nv_bfloat16* sghi = s_sm;
    __nv_bfloat16* sglo = s_sm + S_TILE;
    __nv_bfloat16* sfhi = s_sm + 2 * S_TILE;
    __nv_bfloat16* sflo = s_sm + 3 * S_TILE;

    // load tiles: 128 rows x 64 d (8 chunks of 16B) per array
    {
        const u32 sb = smem_u32(s_sm);
#pragma unroll
        for (int r = 0; r < 4; r++) {
            int e = tid + 256 * r;               // 1024 entries = 128 x 8
            int row = e >> 3, c16 = e & 7;
            u32 doff = row * (SST * 2) + c16 * 16;
            const size_t gsrc = ((size_t)b * NN + j0 + row) * CQ + c16 * 8;
            const size_t fsrc = ((size_t)b * NN + i0 + row) * CQ + c16 * 8;
            cp16(sb + doff, &d_ghi[gsrc]);
            cp16(sb + S_TILE * 2 + doff, &d_glo[gsrc]);
            cp16(sb + 2 * S_TILE * 2 + doff, &d_fhi[fsrc]);
            cp16(sb + 3 * S_TILE * 2 + doff, &d_flo[fsrc]);
        }
        CP_COMMIT();
        CP_WAIT(0);
    }
    __syncthreads();

    float acc[2][8][4];
#pragma unroll
    for (int mi = 0; mi < 2; mi++)
#pragma unroll
        for (int ni = 0; ni < 8; ni++)
#pragma unroll
            for (int q = 0; q < 4; q++) acc[mi][ni][q] = 0.f;

#pragma unroll
    for (int ks = 0; ks < 4; ks++) {
        const int cA = ks * 16 + 2 * t4;
        u32 ahi[2][4], alo[2][4];
#pragma unroll
        for (int mi = 0; mi < 2; mi++) {
            const int r0 = jw + mi * 16 + g;
            ahi[mi][0] = *(const u32*)&sghi[r0 * SST + cA];
            ahi[mi][1] = *(const u32*)&sghi[(r0 + 8) * SST + cA];
            ahi[mi][2] = *(const u32*)&sghi[r0 * SST + cA + 8];
            ahi[mi][3] = *(const u32*)&sghi[(r0 + 8) * SST + cA + 8];
            alo[mi][0] = *(const u32*)&sglo[r0 * SST + cA];
            alo[mi][1] = *(const u32*)&sglo[(r0 + 8) * SST + cA];
            alo[mi][2] = *(const u32*)&sglo[r0 * SST + cA + 8];
            alo[mi][3] = *(const u32*)&sglo[(r0 + 8) * SST + cA + 8];
        }
#pragma unroll
        for (int ni = 0; ni < 8; ni++) {
            const int nr = iw + ni * 8 + g;
            u32 bh0 = *(const u32*)&sfhi[nr * SST + cA];
            u32 bh1 = *(const u32*)&sfhi[nr * SST + cA + 8];
            u32 bl0 = *(const u32*)&sflo[nr * SST + cA];
            u32 bl1 = *(const u32*)&sflo[nr * SST + cA + 8];
#pragma unroll
            for (int mi = 0; mi < 2; mi++) {
                mma_bf16(acc[mi][ni], ahi[mi], bh0, bh1);
                mma_bf16(acc[mi][ni], ahi[mi], bl0, bl1);
                mma_bf16(acc[mi][ni], alo[mi], bh0, bh1);
            }
        }
    }

    // store S fp32
#pragma unroll
    for (int mi = 0; mi < 2; mi++) {
        const int m0 = j0 + jw + mi * 16 + g;
#pragma unroll
        for (int ni = 0; ni < 8; ni++) {
            const int ic = i0 + iw + ni * 8 + 2 * t4;
            *(u64*)&d_S[(size_t)m0 * NN + ic] = pack2(acc[mi][ni][0], acc[mi][ni][1]);
            *(u64*)&d_S[(size_t)(m0 + 8) * NN + ic] = pack2(acc[mi][ni][2], acc[mi][ni][3]);
        }
    }
}

// ---------------- 4) row softmax over i; emit P as bf16 hi/lo ----------------
__global__ void __launch_bounds__(256) softmax_kernel() {
    const int j = blockIdx.x;
    const float* row = d_S + (size_t)j * NN;
    const int tid = threadIdx.x;
    const int lane = tid & 31, warp = tid >> 5;
    __shared__ float red[8];
    __shared__ float bcast;

    float4 v[4];
#pragma unroll
    for (int r = 0; r < 4; r++) v[r] = *(const float4*)&row[(tid + 256 * r) * 4];

    float m = -INFINITY;
#pragma unroll
    for (int r = 0; r < 4; r++)
        m = fmaxf(m, fmaxf(fmaxf(v[r].x, v[r].y), fmaxf(v[r].z, v[r].w)));
#pragma unroll
    for (int o = 16; o > 0; o >>= 1) m = fmaxf(m, __shfl_xor_sync(0xFFFFFFFFu, m, o));
    if (lane == 0) red[warp] = m;
    __syncthreads();
    if (tid == 0) {
        float mm = red[0];
#pragma unroll
        for (int i = 1; i < 8; i++) mm = fmaxf(mm, red[i]);
        bcast = mm;
    }
    __syncthreads();
    const float M = bcast;

    float s = 0.f;
#pragma unroll
    for (int r = 0; r < 4; r++) {
        v[r].x = __expf(v[r].x - M); v[r].y = __expf(v[r].y - M);
        v[r].z = __expf(v[r].z - M); v[r].w = __expf(v[r].w - M);
        s += v[r].x + v[r].y + v[r].z + v[r].w;
    }
#pragma unroll
    for (int o = 16; o > 0; o >>= 1) s += __shfl_xor_sync(0xFFFFFFFFu, s, o);
    if (lane == 0) red[warp] = s;
    __syncthreads();
    if (tid == 0) {
        float ss = 0.f;
#pragma unroll
        for (int i = 0; i < 8; i++) ss += red[i];
        bcast = 1.f / ss;
    }
    __syncthreads();
    const float inv = bcast;
    const size_t ro = (size_t)j * NN;
#pragma unroll
    for (int r = 0; r < 4; r++) {
        float p0 = v[r].x * inv, p1 = v[r].y * inv, p2 = v[r].z * inv, p3 = v[r].w * inv;
        float h0 = bfround(p0), h1 = bfround(p1), h2 = bfround(p2), h3 = bfround(p3);
        uint2 ph; ph.x = bf2(h0, h1); ph.y = bf2(h2, h3);
        uint2 pl; pl.x = bf2(p0 - h0, p1 - h1); pl.y = bf2(p2 - h2, p3 - h3);
        const size_t idx = ro + (size_t)(tid + 256 * r) * 4;
        *(uint2*)&d_Phi[idx] = ph;
        *(uint2*)&d_Plo[idx] = pl;
    }
}

// ---------------- 5) PV via mma.sync (3-term split), R9 tiling + ldmatrix --------
// CTA 128j x 128c. 8 warps (wm 0..3)x(wn 0..1) -> 32j x 64c. K chunks of 32,
// double-buffered cp.async. Fragments loaded with ldmatrix.x4.
#define TSTRIDE 40
#define TILE_BF (128 * TSTRIDE)       // 5120 bf16 per array
#define STAGE_BF (4 * TILE_BF)        // Ahi, Alo, Bhi, Blo
#define PV_SMEM (2 * STAGE_BF * 2)    // 81920 B

extern __shared__ __nv_bfloat16 pv_sm[];

__device__ __forceinline__ void pv_load_stage(
    __nv_bfloat16* st, const __nv_bfloat16* Hhi, const __nv_bfloat16* Hlo,
    int j0, int c0, int kc, int tid) {
    const u32 sb = smem_u32(st);
#pragma unroll
    for (int r = 0; r < 2; r++) {                 // A: 128 rows x 4 chunks
        int e = tid + 256 * r;
        int row = e >> 2, c16 = e & 3;
        const size_t src = (size_t)(j0 + row) * NN + kc + c16 * 8;
        u32 dst = sb + row * (TSTRIDE * 2) + c16 * 16;
        cp16(dst, &d_Phi[src]);
        cp16(dst + TILE_BF * 2, &d_Plo[src]);
    }
#pragma unroll
    for (int r = 0; r < 2; r++) {                 // B: 128 rows x 4 chunks
        int e = tid + 256 * r;
        int row = e >> 2, c16 = e & 3;
        const size_t src = (size_t)(c0 + row) * NN + kc + c16 * 8;
        u32 dst = sb + 2 * (TILE_BF * 2) + row * (TSTRIDE * 2) + c16 * 16;
        cp16(dst, &Hhi[src]);
        cp16(dst + TILE_BF * 2, &Hlo[src]);
    }
    CP_COMMIT();
}

__global__ void __launch_bounds__(256, 2) pv_kernel(
    int b, const float* __restrict__ x, const float* __restrict__ gamma,
    float* __restrict__ out) {
    const int j0 = blockIdx.x * 128;
    const int c0 = blockIdx.y * 128;
    const int tid = threadIdx.x;
    const int lane = tid & 31, wid = tid >> 5;
    const int g = lane >> 2, t4 = lane & 3;
    const int jw = (wid >> 1) * 32;               // warp j offset
    const int cw = (wid & 1) * 64;                // warp c offset

    const __nv_bfloat16* Hhi = d_hThi + (size_t)b * CC * NN;
    const __nv_bfloat16* Hlo = d_hTlo + (size_t)b * CC * NN;

    // per-lane ldmatrix offsets (bytes within one array tile)
    const int rowA = lane & 15, khalf = lane >> 4;        // A: x4 = a0..a3
    u32 offA[2];
#pragma unroll
    for (int mi = 0; mi < 2; mi++)
        offA[mi] = (u32)((jw + mi * 16 + rowA) * (TSTRIDE * 2) + khalf * 16);
    const int grp = lane >> 3, row8 = lane & 7;           // B: x4 = {b0,b1} x 2 ni
    u32 offB[4];
#pragma unroll
    for (int p = 0; p < 4; p++)
        offB[p] = (u32)((cw + (2 * p + (grp >> 1)) * 8 + row8) * (TSTRIDE * 2) + (grp & 1) * 16);

    float acc[2][8][4];
#pragma unroll
    for (int mi = 0; mi < 2; mi++)
#pragma unroll
        for (int ni = 0; ni < 8; ni++)
#pragma unroll
            for (int q = 0; q < 4; q++) acc[mi][ni][q] = 0.f;

    pv_load_stage(pv_sm, Hhi, Hlo, j0, c0, 0, tid);

    const u32 smb = smem_u32(pv_sm);
    for (int tch = 0; tch < 128; tch++) {
        if (tch + 1 < 128) {
            pv_load_stage(pv_sm + ((tch + 1) & 1) * STAGE_BF, Hhi, Hlo,
                          j0, c0, (tch + 1) * 32, tid);
            CP_WAIT(1);
        } else {
            CP_WAIT(0);
        }
        __syncthreads();

        const u32 stb  = smb + (u32)((tch & 1) * STAGE_BF * 2);
        const u32 bAhi = stb;
        const u32 bAlo = stb + TILE_BF * 2;
        const u32 bBhi = stb + 2 * (TILE_BF * 2);
        const u32 bBlo = stb + 3 * (TILE_BF * 2);

#pragma unroll
        for (int s = 0; s < 2; s++) {
            const u32 sOff = s * 32;              // 16 bf16 = 32 B
            u32 ahi[2][4], alo[2][4];
#pragma unroll
            for (int mi = 0; mi < 2; mi++) {
                ldsm_x4(ahi[mi], bAhi + offA[mi] + sOff);
                ldsm_x4(alo[mi], bAlo + offA[mi] + sOff);
            }
#pragma unroll
            for (int p = 0; p < 4; p++) {
                u32 bh[4], bl[4];
                ldsm_x4(bh, bBhi + offB[p] + sOff);
                ldsm_x4(bl, bBlo + offB[p] + sOff);
#pragma unroll
                for (int mi = 0; mi < 2; mi++) {
                    mma_bf16(acc[mi][2 * p],     ahi[mi], bh[0], bh[1]);  // hi*hi
                    mma_bf16(acc[mi][2 * p],     ahi[mi], bl[0], bl[1]);  // hi*lo
                    mma_bf16(acc[mi][2 * p],     alo[mi], bh[0], bh[1]);  // lo*hi
                    mma_bf16(acc[mi][2 * p + 1], ahi[mi], bh[2], bh[3]);
                    mma_bf16(acc[mi][2 * p + 1], ahi[mi], bl[2], bl[3]);
                    mma_bf16(acc[mi][2 * p + 1], alo[mi], bh[2], bh[3]);
                }
            }
        }
        __syncthreads();
    }

    // epilogue: y[b,c,j] = gamma * o + x
    const float gam = gamma[0];
    const size_t xb = (size_t)b * CC * NN;
#pragma unroll
    for (int mi = 0; mi < 2; mi++) {
        const int m0 = j0 + jw + mi * 16 + g;
#pragma unroll
        for (int ni = 0; ni < 8; ni++) {
            const int n0 = c0 + cw + ni * 8 + 2 * t4;
            const size_t i00 = xb + (size_t)n0 * NN + m0;
            const size_t i01 = i00 + NN;
            out[i00]     = gam * acc[mi][ni][0] + x[i00];
            out[i01]     = gam * acc[mi][ni][1] + x[i01];
            out[i00 + 8] = gam * acc[mi][ni][2] + x[i00 + 8];
            out[i01 + 8] = gam * acc[mi][ni][3] + x[i01 + 8];
        }
    }
}

// ---------------- launch ----------------
extern "C" void kernel_launch(void* const* d_in, const int* in_sizes, int n_in,
                              void* d_out, int out_size) {
    (void)in_sizes; (void)n_in; (void)out_size;
    const float* x     = (const float*)d_in[0];
    const float* Wf    = (const float*)d_in[1];
    const float* bf    = (const float*)d_in[2];
    const float* Wg    = (const float*)d_in[3];
    const float* bg    = (const float*)d_in[4];
    const float* Wh    = (const float*)d_in[5];
    const float* bh    = (const float*)d_in[6];
    const float* gamma = (const float*)d_in[7];
    const float* uf    = (const float*)d_in[8];
    const float* ug    = (const float*)d_in[9];
    const float* uh    = (const float*)d_in[10];
    float* out = (float*)d_out;

    cudaFuncSetAttribute(s_kernel, cudaFuncAttributeMaxDynamicSharedMemorySize, S_SMEM);
    cudaFuncSetAttribute(pv_kernel, cudaFuncAttributeMaxDynamicSharedMemorySize, PV_SMEM);

    sigma_kernel<<<3, 512>>>(Wf, Wg, Wh, uf, ug, uh);
    proj_kernel<<<dim3(NN / 64, 10, BB), dim3(16, 16)>>>(x, Wf, bf, Wg, bg, Wh, bh);
    for (int b = 0; b < BB; b++) {
        s_kernel<<<dim3(NN / 128, NN / 128), 256, S_SMEM>>>(b);
        softmax_kernel<<<NN, 256>>>();
        pv_kernel<<<dim3(NN / 128, CC / 128), 256, PV_SMEM>>>(b, x, gamma, out);
    }
}

// round 13
// speedup vs baseline: 1.5215x; 1.2368x over previous
#include <cuda_runtime.h>
#include <cuda_fp16.h>
#include <math.h>
#include <stdint.h>

#define BB 8
#define CC 512
#define CQ 64
#define NN 4096   // H*W

typedef unsigned long long u64;
typedef unsigned int u32;

// ---------------- packed fp32x2 helpers ----------------
__device__ __forceinline__ u64 pack2(float lo, float hi) {
    u64 r; asm("mov.b64 %0, {%1, %2};" : "=l"(r) : "f"(lo), "f"(hi)); return r;
}
__device__ __forceinline__ void unpack2(u64 v, float& lo, float& hi) {
    asm("mov.b64 {%0, %1}, %2;" : "=f"(lo), "=f"(hi) : "l"(v));
}
__device__ __forceinline__ u64 ffma2(u64 a, u64 b, u64 c) {
    u64 d; asm("fma.rn.f32x2 %0, %1, %2, %3;" : "=l"(d) : "l"(a), "l"(b), "l"(c)); return d;
}

// fp16 pair pack: element order in memory = (lo_elem, hi_elem)
__device__ __forceinline__ u32 f16x2(float lo, float hi) {
    u32 r; asm("cvt.rn.f16x2.f32 %0, %1, %2;" : "=r"(r) : "f"(hi), "f"(lo)); return r;
}

// ---------------- cp.async / smem helpers ----------------
__device__ __forceinline__ u32 smem_u32(const void* p) {
    u32 a;
    asm("{ .reg .u64 t; cvta.to.shared.u64 t, %1; cvt.u32.u64 %0, t; }" : "=r"(a) : "l"(p));
    return a;
}
__device__ __forceinline__ void cp16(u32 s, const void* g) {
    asm volatile("cp.async.cg.shared.global [%0], [%1], 16;" :: "r"(s), "l"(g));
}
#define CP_COMMIT()  asm volatile("cp.async.commit_group;" ::: "memory")
#define CP_WAIT(n)   asm volatile("cp.async.wait_group %0;" :: "n"(n) : "memory")

// ---------------- warp mma.sync fp16 + ldmatrix ----------------
__device__ __forceinline__ void mma_f16(float* c, const u32* a, u32 b0, u32 b1) {
    asm volatile(
        "mma.sync.aligned.m16n8k16.row.col.f32.f16.f16.f32 "
        "{%0,%1,%2,%3}, {%4,%5,%6,%7}, {%8,%9}, {%0,%1,%2,%3};"
        : "+f"(c[0]), "+f"(c[1]), "+f"(c[2]), "+f"(c[3])
        : "r"(a[0]), "r"(a[1]), "r"(a[2]), "r"(a[3]), "r"(b0), "r"(b1));
}
__device__ __forceinline__ void ldsm_x4(u32* r, u32 addr) {
    asm volatile("ldmatrix.sync.aligned.m8n8.x4.shared.b16 {%0,%1,%2,%3}, [%4];"
                 : "=r"(r[0]), "=r"(r[1]), "=r"(r[2]), "=r"(r[3]) : "r"(addr));
}

// ---------------- scratch (144 MB) ----------------
__device__ __half d_f16[(size_t)BB * NN * CQ];            // f (b,i,d)  4 MB
__device__ __half d_g16[(size_t)BB * NN * CQ];            // g (b,j,d)  4 MB
__device__ __half d_hT16[(size_t)BB * CC * NN];           // hT (b,c,i) 8 MB
__device__ float d_S[(size_t)NN * NN];                    // S (1 batch) 64 MB
__device__ __half d_Phi[(size_t)NN * NN];                 // P hi       32 MB
__device__ __half d_Plo[(size_t)NN * NN];                 // P lo       32 MB
__device__ float d_rsig[3];

// ---------------- 1) spectral sigma ----------------
__global__ void sigma_kernel(const float* __restrict__ Wf, const float* __restrict__ Wg,
                             const float* __restrict__ Wh, const float* __restrict__ uf,
                             const float* __restrict__ ug, const float* __restrict__ uh) {
    const int w = blockIdx.x;
    const float* W; const float* u; int M;
    if (w == 0)      { W = Wf; u = uf; M = CQ; }
    else if (w == 1) { W = Wg; u = ug; M = CQ; }
    else             { W = Wh; u = uh; M = CC; }
    const int K = CC;

    __shared__ float t[CC];
    __shared__ float red[CC];
    __shared__ float wsum[16];
    __shared__ float vnorm;
    const int tid = threadIdx.x;
    const int lane = tid & 31, warp = tid >> 5;

    float acc = 0.f;
#pragma unroll 8
    for (int m = 0; m < M; m++) acc += W[m * K + tid] * u[m];
    t[tid] = acc;
    red[tid] = acc * acc;
    __syncthreads();
    for (int s = 256; s > 0; s >>= 1) { if (tid < s) red[tid] += red[tid + s]; __syncthreads(); }
    if (tid == 0) vnorm = sqrtf(red[0]) + 1e-12f;
    __syncthreads();
    t[tid] *= (1.f / vnorm);
    __syncthreads();

    float local = 0.f;
    for (int m = warp; m < M; m += 16) {
        const float* Wr = W + (size_t)m * K;
        float a = 0.f;
#pragma unroll 4
        for (int k = lane; k < K; k += 32) a += Wr[k] * t[k];
#pragma unroll
        for (int o = 16; o > 0; o >>= 1) a += __shfl_xor_sync(0xFFFFFFFFu, a, o);
        local += a * a;
    }
    if (lane == 0) wsum[warp] = local;
    __syncthreads();
    if (tid == 0) {
        float nw2 = 0.f;
#pragma unroll
        for (int i = 0; i < 16; i++) nw2 += wsum[i];
        float nw = sqrtf(nw2);
        d_rsig[w] = (nw + 1e-12f) / nw2;   // 1/sigma
    }
}

// ---------------- 2) projections; f,g,h emitted as fp16 ----------------
__global__ void __launch_bounds__(256) proj_kernel(
    const float* __restrict__ x,
    const float* __restrict__ Wf, const float* __restrict__ bf,
    const float* __restrict__ Wg, const float* __restrict__ bg,
    const float* __restrict__ Wh, const float* __restrict__ bh) {
    const int K = CC;
    const int n0 = blockIdx.x * 64;
    const int o0 = blockIdx.y * 64;
    const int b  = blockIdx.z;

    const float* W; const float* bias; int seg, orow0;
    if (o0 < 64)       { seg = 0; W = Wf; bias = bf; orow0 = o0; }
    else if (o0 < 128) { seg = 1; W = Wg; bias = bg; orow0 = o0 - 64; }
    else               { seg = 2; W = Wh; bias = bh; orow0 = o0 - 128; }

    __shared__ float Ws[32][69];
    __shared__ float xs[32][68];

    const int tid = threadIdx.y * 16 + threadIdx.x;
    const int tx = threadIdx.x, ty = threadIdx.y;

    u64 accp[4][2];
#pragma unroll
    for (int i = 0; i < 4; i++) { accp[i][0] = 0ull; accp[i][1] = 0ull; }

    const size_t xbase = (size_t)b * CC * NN;

    for (int kc = 0; kc < K; kc += 32) {
#pragma unroll
        for (int r = 0; r < 8; r++) {
            int e = tid + 256 * r;
            int kk = e >> 6, nn = e & 63;
            xs[kk][nn] = x[xbase + (size_t)(kc + kk) * NN + n0 + nn];
        }
#pragma unroll
        for (int r = 0; r < 8; r++) {
            int e = tid + 256 * r;
            int kk = e & 31, oo = e >> 5;
            Ws[kk][oo] = W[(size_t)(orow0 + oo) * K + kc + kk];
        }
        __syncthreads();
#pragma unroll
        for (int kk = 0; kk < 32; kk++) {
            ulonglong2 bv = *(const ulonglong2*)&xs[kk][tx * 4];
#pragma unroll
            for (int i = 0; i < 4; i++) {
                float a = Ws[kk][ty * 4 + i];
                u64 A = pack2(a, a);
                accp[i][0] = ffma2(A, bv.x, accp[i][0]);
                accp[i][1] = ffma2(A, bv.y, accp[i][1]);
            }
        }
        __syncthreads();
    }

    const float rs = d_rsig[seg];
    const u64 rs2 = pack2(rs, rs);
    float vv[4][4];                          // [i(d)][j(n)]
#pragma unroll
    for (int i = 0; i < 4; i++) {
        const float bia = bias[orow0 + ty * 4 + i];
        const u64 b2 = pack2(bia, bia);
        u64 r0 = ffma2(accp[i][0], rs2, b2);
        u64 r1 = ffma2(accp[i][1], rs2, b2);
        unpack2(r0, vv[i][0], vv[i][1]);
        unpack2(r1, vv[i][2], vv[i][3]);
    }
    if (seg < 2) {
        __half* Dst = (seg == 0) ? d_f16 : d_g16;
#pragma unroll
        for (int j = 0; j < 4; j++) {        // (b, n, d): 4 consecutive d
            const int n = n0 + tx * 4 + j;
            uint2 p;
            p.x = f16x2(vv[0][j], vv[1][j]);
            p.y = f16x2(vv[2][j], vv[3][j]);
            const size_t base = ((size_t)b * NN + n) * CQ + orow0 + ty * 4;
            *(uint2*)&Dst[base] = p;
        }
    } else {
#pragma unroll
        for (int i = 0; i < 4; i++) {        // hT (b, c, i): 4 consecutive n
            const int orow = orow0 + ty * 4 + i;
            uint2 p;
            p.x = f16x2(vv[i][0], vv[i][1]);
            p.y = f16x2(vv[i][2], vv[i][3]);
            const size_t base = ((size_t)b * CC + orow) * NN + n0 + tx * 4;
            *(uint2*)&d_hT16[base] = p;
        }
    }
}

// ---------------- 3) S = g f^T via single-term fp16 mma ----------------
// CTA 128j x 128i, K=64 single shot. 8 warps: (wm 0..3)x(wn 0..1) -> 32j x 64i.
#define SST 72                         // padded row stride (halfs)
#define S_TILE (128 * SST)             // per array
#define S_SMEM (2 * S_TILE * 2)        // g16, f16  (36864 B)

extern __shared__ __half s_sm[];

__global__ void __launch_bounds__(256, 2) s_kernel(int b) {
    const int j0 = blockIdx.x * 128;
    const int i0 = blockIdx.y * 128;
    const int tid = threadIdx.x;
    const int lane = tid & 31, wid = tid >> 5;
    const int g = lane >> 2, t4 = lane & 3;
    const int jw = (wid >> 1) * 32;
    const int iw = (wid & 1) * 64;

    __half* sg = s_sm;
    __half* sf = s_sm + S_TILE;

    {
        const u32 sb = smem_u32(s_sm);
#pragma unroll
        for (int r = 0; r < 4; r++) {
            int e = tid + 256 * r;               // 1024 entries = 128 rows x 8 chunks
            int row = e >> 3, c16 = e & 7;
            u32 doff = row * (SST * 2) + c16 * 16;
            const size_t gsrc = ((size_t)b * NN + j0 + row) * CQ + c16 * 8;
            const size_t fsrc = ((size_t)b * NN + i0 + row) * CQ + c16 * 8;
            cp16(sb + doff, &d_g16[gsrc]);
            cp16(sb + S_TILE * 2 + doff, &d_f16[fsrc]);
        }
        CP_COMMIT();
        CP_WAIT(0);
    }
    __syncthreads();

    float acc[2][8][4];
#pragma unroll
    for (int mi = 0; mi < 2; mi++)
#pragma unroll
        for (int ni = 0; ni < 8; ni++)
#pragma unroll
            for (int q = 0; q < 4; q++) acc[mi][ni][q] = 0.f;

#pragma unroll
    for (int ks = 0; ks < 4; ks++) {
        const int cA = ks * 16 + 2 * t4;
        u32 a[2][4];
#pragma unroll
        for (int mi = 0; mi < 2; mi++) {
            const int r0 = jw + mi * 16 + g;
            a[mi][0] = *(const u32*)&sg[r0 * SST + cA];
            a[mi][1] = *(const u32*)&sg[(r0 + 8) * SST + cA];
            a[mi][2] = *(const u32*)&sg[r0 * SST + cA + 8];
            a[mi][3] = *(const u32*)&sg[(r0 + 8) * SST + cA + 8];
        }
#pragma unroll
        for (int ni = 0; ni < 8; ni++) {
            const int nr = iw + ni * 8 + g;
            u32 b0 = *(const u32*)&sf[nr * SST + cA];
            u32 b1 = *(const u32*)&sf[nr * SST + cA + 8];
#pragma unroll
            for (int mi = 0; mi < 2; mi++)
                mma_f16(acc[mi][ni], a[mi], b0, b1);
        }
    }

#pragma unroll
    for (int mi = 0; mi < 2; mi++) {
        const int m0 = j0 + jw + mi * 16 + g;
#pragma unroll
        for (int ni = 0; ni < 8; ni++) {
            const int ic = i0 + iw + ni * 8 + 2 * t4;
            *(u64*)&d_S[(size_t)m0 * NN + ic] = pack2(acc[mi][ni][0], acc[mi][ni][1]);
            *(u64*)&d_S[(size_t)(m0 + 8) * NN + ic] = pack2(acc[mi][ni][2], acc[mi][ni][3]);
        }
    }
}

// ---------------- 4) row softmax over i; emit P as fp16 hi/lo ----------------
__global__ void __launch_bounds__(256) softmax_kernel() {
    const int j = blockIdx.x;
    const float* row = d_S + (size_t)j * NN;
    const int tid = threadIdx.x;
    const int lane = tid & 31, warp = tid >> 5;
    __shared__ float red[8];
    __shared__ float bcast;

    float4 v[4];
#pragma unroll
    for (int r = 0; r < 4; r++) v[r] = *(const float4*)&row[(tid + 256 * r) * 4];

    float m = -INFINITY;
#pragma unroll
    for (int r = 0; r < 4; r++)
        m = fmaxf(m, fmaxf(fmaxf(v[r].x, v[r].y), fmaxf(v[r].z, v[r].w)));
#pragma unroll
    for (int o = 16; o > 0; o >>= 1) m = fmaxf(m, __shfl_xor_sync(0xFFFFFFFFu, m, o));
    if (lane == 0) red[warp] = m;
    __syncthreads();
    if (tid == 0) {
        float mm = red[0];
#pragma unroll
        for (int i = 1; i < 8; i++) mm = fmaxf(mm, red[i]);
        bcast = mm;
    }
    __syncthreads();
    const float M = bcast;

    float s = 0.f;
#pragma unroll
    for (int r = 0; r < 4; r++) {
        v[r].x = __expf(v[r].x - M); v[r].y = __expf(v[r].y - M);
        v[r].z = __expf(v[r].z - M); v[r].w = __expf(v[r].w - M);
        s += v[r].x + v[r].y + v[r].z + v[r].w;
    }
#pragma unroll
    for (int o = 16; o > 0; o >>= 1) s += __shfl_xor_sync(0xFFFFFFFFu, s, o);
    if (lane == 0) red[warp] = s;
    __syncthreads();
    if (tid == 0) {
        float ss = 0.f;
#pragma unroll
        for (int i = 0; i < 8; i++) ss += red[i];
        bcast = 1.f / ss;
    }
    __syncthreads();
    const float inv = bcast;
    const size_t ro = (size_t)j * NN;
#pragma unroll
    for (int r = 0; r < 4; r++) {
        float p0 = v[r].x * inv, p1 = v[r].y * inv, p2 = v[r].z * inv, p3 = v[r].w * inv;
        float h0 = __half2float(__float2half_rn(p0));
        float h1 = __half2float(__float2half_rn(p1));
        float h2 = __half2float(__float2half_rn(p2));
        float h3 = __half2float(__float2half_rn(p3));
        uint2 ph; ph.x = f16x2(h0, h1); ph.y = f16x2(h2, h3);
        uint2 pl; pl.x = f16x2(p0 - h0, p1 - h1); pl.y = f16x2(p2 - h2, p3 - h3);
        const size_t idx = ro + (size_t)(tid + 256 * r) * 4;
        *(uint2*)&d_Phi[idx] = ph;
        *(uint2*)&d_Plo[idx] = pl;
    }
}

// ---------------- 5) PV via mma.sync fp16 (2-term: Phi*H + Plo*H) ----------------
// CTA 128j x 128c. 8 warps (wm 0..3)x(wn 0..1) -> 32j x 64c. K chunks of 32,
// double-buffered cp.async. Fragments via ldmatrix.x4.
#define TSTRIDE 40
#define TILE_BF (128 * TSTRIDE)       // 5120 halfs per array
#define STAGE_BF (3 * TILE_BF)        // Phi, Plo, H16
#define PV_SMEM (2 * STAGE_BF * 2)    // 61440 B

extern __shared__ __half pv_sm[];

__device__ __forceinline__ void pv_load_stage(
    __half* st, const __half* H16, int j0, int c0, int kc, int tid) {
    const u32 sb = smem_u32(st);
#pragma unroll
    for (int r = 0; r < 2; r++) {                 // A: 128 rows x 4 chunks (Phi + Plo)
        int e = tid + 256 * r;
        int row = e >> 2, c16 = e & 3;
        const size_t src = (size_t)(j0 + row) * NN + kc + c16 * 8;
        u32 dst = sb + row * (TSTRIDE * 2) + c16 * 16;
        cp16(dst, &d_Phi[src]);
        cp16(dst + TILE_BF * 2, &d_Plo[src]);
    }
#pragma unroll
    for (int r = 0; r < 2; r++) {                 // B: 128 rows x 4 chunks (H16)
        int e = tid + 256 * r;
        int row = e >> 2, c16 = e & 3;
        const size_t src = (size_t)(c0 + row) * NN + kc + c16 * 8;
        u32 dst = sb + 2 * (TILE_BF * 2) + row * (TSTRIDE * 2) + c16 * 16;
        cp16(dst, &H16[src]);
    }
    CP_COMMIT();
}

__global__ void __launch_bounds__(256, 2) pv_kernel(
    int b, const float* __restrict__ x, const float* __restrict__ gamma,
    float* __restrict__ out) {
    const int j0 = blockIdx.x * 128;
    const int c0 = blockIdx.y * 128;
    const int tid = threadIdx.x;
    const int lane = tid & 31, wid = tid >> 5;
    const int g = lane >> 2, t4 = lane & 3;
    const int jw = (wid >> 1) * 32;               // warp j offset
    const int cw = (wid & 1) * 64;                // warp c offset

    const __half* H16 = d_hT16 + (size_t)b * CC * NN;

    // per-lane ldmatrix offsets (bytes within one array tile)
    const int rowA = lane & 15, khalf = lane >> 4;        // A: x4 = a0..a3
    u32 offA[2];
#pragma unroll
    for (int mi = 0; mi < 2; mi++)
        offA[mi] = (u32)((jw + mi * 16 + rowA) * (TSTRIDE * 2) + khalf * 16);
    const int grp = lane >> 3, row8 = lane & 7;           // B: x4 = {b0,b1} x 2 ni
    u32 offB[4];
#pragma unroll
    for (int p = 0; p < 4; p++)
        offB[p] = (u32)((cw + (2 * p + (grp >> 1)) * 8 + row8) * (TSTRIDE * 2) + (grp & 1) * 16);

    float acc[2][8][4];
#pragma unroll
    for (int mi = 0; mi < 2; mi++)
#pragma unroll
        for (int ni = 0; ni < 8; ni++)
#pragma unroll
            for (int q = 0; q < 4; q++) acc[mi][ni][q] = 0.f;

    pv_load_stage(pv_sm, H16, j0, c0, 0, tid);

    const u32 smb = smem_u32(pv_sm);
    for (int tch = 0; tch < 128; tch++) {
        if (tch + 1 < 128) {
            pv_load_stage(pv_sm + ((tch + 1) & 1) * STAGE_BF, H16,
                          j0, c0, (tch + 1) * 32, tid);
            CP_WAIT(1);
        } else {
            CP_WAIT(0);
        }
        __syncthreads();

        const u32 stb  = smb + (u32)((tch & 1) * STAGE_BF * 2);
        const u32 bAhi = stb;
        const u32 bAlo = stb + TILE_BF * 2;
        const u32 bB   = stb + 2 * (TILE_BF * 2);

#pragma unroll
        for (int s = 0; s < 2; s++) {
            const u32 sOff = s * 32;              // 16 halfs = 32 B
            u32 ahi[2][4], alo[2][4];
#pragma unroll
            for (int mi = 0; mi < 2; mi++) {
                ldsm_x4(ahi[mi], bAhi + offA[mi] + sOff);
                ldsm_x4(alo[mi], bAlo + offA[mi] + sOff);
            }
#pragma unroll
            for (int p = 0; p < 4; p++) {
                u32 bh[4];
                ldsm_x4(bh, bB + offB[p] + sOff);
#pragma unroll
                for (int mi = 0; mi < 2; mi++) {
                    mma_f16(acc[mi][2 * p],     ahi[mi], bh[0], bh[1]);  // Phi*H
                    mma_f16(acc[mi][2 * p],     alo[mi], bh[0], bh[1]);  // Plo*H
                    mma_f16(acc[mi][2 * p + 1], ahi[mi], bh[2], bh[3]);
                    mma_f16(acc[mi][2 * p + 1], alo[mi], bh[2], bh[3]);
                }
            }
        }
        __syncthreads();
    }

    // epilogue: y[b,c,j] = gamma * o + x
    const float gam = gamma[0];
    const size_t xb = (size_t)b * CC * NN;
#pragma unroll
    for (int mi = 0; mi < 2; mi++) {
        const int m0 = j0 + jw + mi * 16 + g;
#pragma unroll
        for (int ni = 0; ni < 8; ni++) {
            const int n0 = c0 + cw + ni * 8 + 2 * t4;
            const size_t i00 = xb + (size_t)n0 * NN + m0;
            const size_t i01 = i00 + NN;
            out[i00]     = gam * acc[mi][ni][0] + x[i00];
            out[i01]     = gam * acc[mi][ni][1] + x[i01];
            out[i00 + 8] = gam * acc[mi][ni][2] + x[i00 + 8];
            out[i01 + 8] = gam * acc[mi][ni][3] + x[i01 + 8];
        }
    }
}

// ---------------- launch ----------------
extern "C" void kernel_launch(void* const* d_in, const int* in_sizes, int n_in,
                              void* d_out, int out_size) {
    (void)in_sizes; (void)n_in; (void)out_size;
    const float* x     = (const float*)d_in[0];
    const float* Wf    = (const float*)d_in[1];
    const float* bf    = (const float*)d_in[2];
    const float* Wg    = (const float*)d_in[3];
    const float* bg    = (const float*)d_in[4];
    const float* Wh    = (const float*)d_in[5];
    const float* bh    = (const float*)d_in[6];
    const float* gamma = (const float*)d_in[7];
    const float* uf    = (const float*)d_in[8];
    const float* ug    = (const float*)d_in[9];
    const float* uh    = (const float*)d_in[10];
    float* out = (float*)d_out;

    cudaFuncSetAttribute(s_kernel, cudaFuncAttributeMaxDynamicSharedMemorySize, S_SMEM);
    cudaFuncSetAttribute(pv_kernel, cudaFuncAttributeMaxDynamicSharedMemorySize, PV_SMEM);

    sigma_kernel<<<3, 512>>>(Wf, Wg, Wh, uf, ug, uh);
    proj_kernel<<<dim3(NN / 64, 10, BB), dim3(16, 16)>>>(x, Wf, bf, Wg, bg, Wh, bh);
    for (int b = 0; b < BB; b++) {
        s_kernel<<<dim3(NN / 128, NN / 128), 256, S_SMEM>>>(b);
        softmax_kernel<<<NN, 256>>>();
        pv_kernel<<<dim3(NN / 128, CC / 128), 256, PV_SMEM>>>(b, x, gamma, out);
    }
}

// round 14
// speedup vs baseline: 1.8192x; 1.1957x over previous
#include <cuda_runtime.h>
#include <cuda_fp16.h>
#include <math.h>
#include <stdint.h>

#define BB 8
#define CC 512
#define CQ 64
#define NN 4096   // H*W

typedef unsigned long long u64;
typedef unsigned int u32;

// ---------------- packed fp32x2 helpers ----------------
__device__ __forceinline__ u64 pack2(float lo, float hi) {
    u64 r; asm("mov.b64 %0, {%1, %2};" : "=l"(r) : "f"(lo), "f"(hi)); return r;
}
__device__ __forceinline__ void unpack2(u64 v, float& lo, float& hi) {
    asm("mov.b64 {%0, %1}, %2;" : "=f"(lo), "=f"(hi) : "l"(v));
}
__device__ __forceinline__ u64 ffma2(u64 a, u64 b, u64 c) {
    u64 d; asm("fma.rn.f32x2 %0, %1, %2, %3;" : "=l"(d) : "l"(a), "l"(b), "l"(c)); return d;
}

// fp16 pair pack: element order in memory = (lo_elem, hi_elem)
__device__ __forceinline__ u32 f16x2(float lo, float hi) {
    u32 r; asm("cvt.rn.f16x2.f32 %0, %1, %2;" : "=r"(r) : "f"(hi), "f"(lo)); return r;
}

// ---------------- cp.async / smem helpers ----------------
__device__ __forceinline__ u32 smem_u32(const void* p) {
    u32 a;
    asm("{ .reg .u64 t; cvta.to.shared.u64 t, %1; cvt.u32.u64 %0, t; }" : "=r"(a) : "l"(p));
    return a;
}
__device__ __forceinline__ void cp16(u32 s, const void* g) {
    asm volatile("cp.async.cg.shared.global [%0], [%1], 16;" :: "r"(s), "l"(g));
}
#define CP_COMMIT()  asm volatile("cp.async.commit_group;" ::: "memory")
#define CP_WAIT(n)   asm volatile("cp.async.wait_group %0;" :: "n"(n) : "memory")

// ---------------- warp mma.sync fp16 + ldmatrix ----------------
__device__ __forceinline__ void mma_f16(float* c, const u32* a, u32 b0, u32 b1) {
    asm volatile(
        "mma.sync.aligned.m16n8k16.row.col.f32.f16.f16.f32 "
        "{%0,%1,%2,%3}, {%4,%5,%6,%7}, {%8,%9}, {%0,%1,%2,%3};"
        : "+f"(c[0]), "+f"(c[1]), "+f"(c[2]), "+f"(c[3])
        : "r"(a[0]), "r"(a[1]), "r"(a[2]), "r"(a[3]), "r"(b0), "r"(b1));
}
__device__ __forceinline__ void ldsm_x4(u32* r, u32 addr) {
    asm volatile("ldmatrix.sync.aligned.m8n8.x4.shared.b16 {%0,%1,%2,%3}, [%4];"
                 : "=r"(r[0]), "=r"(r[1]), "=r"(r[2]), "=r"(r[3]) : "r"(addr));
}

// ---------------- scratch (112 MB) ----------------
__device__ __half d_f16[(size_t)BB * NN * CQ];            // f (b,i,d)  4 MB
__device__ __half d_g16[(size_t)BB * NN * CQ];            // g (b,j,d)  4 MB
__device__ __half d_hT16[(size_t)BB * CC * NN];           // hT (b,c,i) 8 MB
__device__ float d_S[(size_t)NN * NN];                    // S (1 batch) 64 MB
__device__ __half d_P16[(size_t)NN * NN];                 // P fp16     32 MB
__device__ float d_rsig[3];

// ---------------- 1) spectral sigma ----------------
__global__ void sigma_kernel(const float* __restrict__ Wf, const float* __restrict__ Wg,
                             const float* __restrict__ Wh, const float* __restrict__ uf,
                             const float* __restrict__ ug, const float* __restrict__ uh) {
    const int w = blockIdx.x;
    const float* W; const float* u; int M;
    if (w == 0)      { W = Wf; u = uf; M = CQ; }
    else if (w == 1) { W = Wg; u = ug; M = CQ; }
    else             { W = Wh; u = uh; M = CC; }
    const int K = CC;

    __shared__ float t[CC];
    __shared__ float red[CC];
    __shared__ float wsum[16];
    __shared__ float vnorm;
    const int tid = threadIdx.x;
    const int lane = tid & 31, warp = tid >> 5;

    float acc = 0.f;
#pragma unroll 8
    for (int m = 0; m < M; m++) acc += W[m * K + tid] * u[m];
    t[tid] = acc;
    red[tid] = acc * acc;
    __syncthreads();
    for (int s = 256; s > 0; s >>= 1) { if (tid < s) red[tid] += red[tid + s]; __syncthreads(); }
    if (tid == 0) vnorm = sqrtf(red[0]) + 1e-12f;
    __syncthreads();
    t[tid] *= (1.f / vnorm);
    __syncthreads();

    float local = 0.f;
    for (int m = warp; m < M; m += 16) {
        const float* Wr = W + (size_t)m * K;
        float a = 0.f;
#pragma unroll 4
        for (int k = lane; k < K; k += 32) a += Wr[k] * t[k];
#pragma unroll
        for (int o = 16; o > 0; o >>= 1) a += __shfl_xor_sync(0xFFFFFFFFu, a, o);
        local += a * a;
    }
    if (lane == 0) wsum[warp] = local;
    __syncthreads();
    if (tid == 0) {
        float nw2 = 0.f;
#pragma unroll
        for (int i = 0; i < 16; i++) nw2 += wsum[i];
        float nw = sqrtf(nw2);
        d_rsig[w] = (nw + 1e-12f) / nw2;   // 1/sigma
    }
}

// ---------------- 2) projections; f,g,h emitted as fp16 ----------------
__global__ void __launch_bounds__(256) proj_kernel(
    const float* __restrict__ x,
    const float* __restrict__ Wf, const float* __restrict__ bf,
    const float* __restrict__ Wg, const float* __restrict__ bg,
    const float* __restrict__ Wh, const float* __restrict__ bh) {
    const int K = CC;
    const int n0 = blockIdx.x * 64;
    const int o0 = blockIdx.y * 64;
    const int b  = blockIdx.z;

    const float* W; const float* bias; int seg, orow0;
    if (o0 < 64)       { seg = 0; W = Wf; bias = bf; orow0 = o0; }
    else if (o0 < 128) { seg = 1; W = Wg; bias = bg; orow0 = o0 - 64; }
    else               { seg = 2; W = Wh; bias = bh; orow0 = o0 - 128; }

    __shared__ float Ws[32][69];
    __shared__ float xs[32][68];

    const int tid = threadIdx.y * 16 + threadIdx.x;
    const int tx = threadIdx.x, ty = threadIdx.y;

    u64 accp[4][2];
#pragma unroll
    for (int i = 0; i < 4; i++) { accp[i][0] = 0ull; accp[i][1] = 0ull; }

    const size_t xbase = (size_t)b * CC * NN;

    for (int kc = 0; kc < K; kc += 32) {
#pragma unroll
        for (int r = 0; r < 8; r++) {
            int e = tid + 256 * r;
            int kk = e >> 6, nn = e & 63;
            xs[kk][nn] = x[xbase + (size_t)(kc + kk) * NN + n0 + nn];
        }
#pragma unroll
        for (int r = 0; r < 8; r++) {
            int e = tid + 256 * r;
            int kk = e & 31, oo = e >> 5;
            Ws[kk][oo] = W[(size_t)(orow0 + oo) * K + kc + kk];
        }
        __syncthreads();
#pragma unroll
        for (int kk = 0; kk < 32; kk++) {
            ulonglong2 bv = *(const ulonglong2*)&xs[kk][tx * 4];
#pragma unroll
            for (int i = 0; i < 4; i++) {
                float a = Ws[kk][ty * 4 + i];
                u64 A = pack2(a, a);
                accp[i][0] = ffma2(A, bv.x, accp[i][0]);
                accp[i][1] = ffma2(A, bv.y, accp[i][1]);
            }
        }
        __syncthreads();
    }

    const float rs = d_rsig[seg];
    const u64 rs2 = pack2(rs, rs);
    float vv[4][4];                          // [i(d)][j(n)]
#pragma unroll
    for (int i = 0; i < 4; i++) {
        const float bia = bias[orow0 + ty * 4 + i];
        const u64 b2 = pack2(bia, bia);
        u64 r0 = ffma2(accp[i][0], rs2, b2);
        u64 r1 = ffma2(accp[i][1], rs2, b2);
        unpack2(r0, vv[i][0], vv[i][1]);
        unpack2(r1, vv[i][2], vv[i][3]);
    }
    if (seg < 2) {
        __half* Dst = (seg == 0) ? d_f16 : d_g16;
#pragma unroll
        for (int j = 0; j < 4; j++) {        // (b, n, d): 4 consecutive d
            const int n = n0 + tx * 4 + j;
            uint2 p;
            p.x = f16x2(vv[0][j], vv[1][j]);
            p.y = f16x2(vv[2][j], vv[3][j]);
            const size_t base = ((size_t)b * NN + n) * CQ + orow0 + ty * 4;
            *(uint2*)&Dst[base] = p;
        }
    } else {
#pragma unroll
        for (int i = 0; i < 4; i++) {        // hT (b, c, i): 4 consecutive n
            const int orow = orow0 + ty * 4 + i;
            uint2 p;
            p.x = f16x2(vv[i][0], vv[i][1]);
            p.y = f16x2(vv[i][2], vv[i][3]);
            const size_t base = ((size_t)b * CC + orow) * NN + n0 + tx * 4;
            *(uint2*)&d_hT16[base] = p;
        }
    }
}

// ---------------- 3) S = g f^T via single-term fp16 mma ----------------
// CTA 128j x 128i, K=64 single shot. 8 warps: (wm 0..3)x(wn 0..1) -> 32j x 64i.
#define SST 72                         // padded row stride (halfs)
#define S_TILE (128 * SST)             // per array
#define S_SMEM (2 * S_TILE * 2)        // g16, f16  (36864 B)

extern __shared__ __half s_sm[];

__global__ void __launch_bounds__(256, 2) s_kernel(int b) {
    const int j0 = blockIdx.x * 128;
    const int i0 = blockIdx.y * 128;
    const int tid = threadIdx.x;
    const int lane = tid & 31, wid = tid >> 5;
    const int g = lane >> 2, t4 = lane & 3;
    const int jw = (wid >> 1) * 32;
    const int iw = (wid & 1) * 64;

    __half* sg = s_sm;
    __half* sf = s_sm + S_TILE;

    {
        const u32 sb = smem_u32(s_sm);
#pragma unroll
        for (int r = 0; r < 4; r++) {
            int e = tid + 256 * r;               // 1024 entries = 128 rows x 8 chunks
            int row = e >> 3, c16 = e & 7;
            u32 doff = row * (SST * 2) + c16 * 16;
            const size_t gsrc = ((size_t)b * NN + j0 + row) * CQ + c16 * 8;
            const size_t fsrc = ((size_t)b * NN + i0 + row) * CQ + c16 * 8;
            cp16(sb + doff, &d_g16[gsrc]);
            cp16(sb + S_TILE * 2 + doff, &d_f16[fsrc]);
        }
        CP_COMMIT();
        CP_WAIT(0);
    }
    __syncthreads();

    float acc[2][8][4];
#pragma unroll
    for (int mi = 0; mi < 2; mi++)
#pragma unroll
        for (int ni = 0; ni < 8; ni++)
#pragma unroll
            for (int q = 0; q < 4; q++) acc[mi][ni][q] = 0.f;

#pragma unroll
    for (int ks = 0; ks < 4; ks++) {
        const int cA = ks * 16 + 2 * t4;
        u32 a[2][4];
#pragma unroll
        for (int mi = 0; mi < 2; mi++) {
            const int r0 = jw + mi * 16 + g;
            a[mi][0] = *(const u32*)&sg[r0 * SST + cA];
            a[mi][1] = *(const u32*)&sg[(r0 + 8) * SST + cA];
            a[mi][2] = *(const u32*)&sg[r0 * SST + cA + 8];
            a[mi][3] = *(const u32*)&sg[(r0 + 8) * SST + cA + 8];
        }
#pragma unroll
        for (int ni = 0; ni < 8; ni++) {
            const int nr = iw + ni * 8 + g;
            u32 b0 = *(const u32*)&sf[nr * SST + cA];
            u32 b1 = *(const u32*)&sf[nr * SST + cA + 8];
#pragma unroll
            for (int mi = 0; mi < 2; mi++)
                mma_f16(acc[mi][ni], a[mi], b0, b1);
        }
    }

#pragma unroll
    for (int mi = 0; mi < 2; mi++) {
        const int m0 = j0 + jw + mi * 16 + g;
#pragma unroll
        for (int ni = 0; ni < 8; ni++) {
            const int ic = i0 + iw + ni * 8 + 2 * t4;
            *(u64*)&d_S[(size_t)m0 * NN + ic] = pack2(acc[mi][ni][0], acc[mi][ni][1]);
            *(u64*)&d_S[(size_t)(m0 + 8) * NN + ic] = pack2(acc[mi][ni][2], acc[mi][ni][3]);
        }
    }
}

// ---------------- 4) row softmax over i; emit P as single fp16 ----------------
__global__ void __launch_bounds__(256) softmax_kernel() {
    const int j = blockIdx.x;
    const float* row = d_S + (size_t)j * NN;
    const int tid = threadIdx.x;
    const int lane = tid & 31, warp = tid >> 5;
    __shared__ float red[8];
    __shared__ float bcast;

    float4 v[4];
#pragma unroll
    for (int r = 0; r < 4; r++) v[r] = *(const float4*)&row[(tid + 256 * r) * 4];

    float m = -INFINITY;
#pragma unroll
    for (int r = 0; r < 4; r++)
        m = fmaxf(m, fmaxf(fmaxf(v[r].x, v[r].y), fmaxf(v[r].z, v[r].w)));
#pragma unroll
    for (int o = 16; o > 0; o >>= 1) m = fmaxf(m, __shfl_xor_sync(0xFFFFFFFFu, m, o));
    if (lane == 0) red[warp] = m;
    __syncthreads();
    if (tid == 0) {
        float mm = red[0];
#pragma unroll
        for (int i = 1; i < 8; i++) mm = fmaxf(mm, red[i]);
        bcast = mm;
    }
    __syncthreads();
    const float M = bcast;

    float s = 0.f;
#pragma unroll
    for (int r = 0; r < 4; r++) {
        v[r].x = __expf(v[r].x - M); v[r].y = __expf(v[r].y - M);
        v[r].z = __expf(v[r].z - M); v[r].w = __expf(v[r].w - M);
        s += v[r].x + v[r].y + v[r].z + v[r].w;
    }
#pragma unroll
    for (int o = 16; o > 0; o >>= 1) s += __shfl_xor_sync(0xFFFFFFFFu, s, o);
    if (lane == 0) red[warp] = s;
    __syncthreads();
    if (tid == 0) {
        float ss = 0.f;
#pragma unroll
        for (int i = 0; i < 8; i++) ss += red[i];
        bcast = 1.f / ss;
    }
    __syncthreads();
    const float inv = bcast;
    const size_t ro = (size_t)j * NN;
#pragma unroll
    for (int r = 0; r < 4; r++) {
        uint2 p;
        p.x = f16x2(v[r].x * inv, v[r].y * inv);
        p.y = f16x2(v[r].z * inv, v[r].w * inv);
        const size_t idx = ro + (size_t)(tid + 256 * r) * 4;
        *(uint2*)&d_P16[idx] = p;
    }
}

// ---------------- 5) PV via mma.sync fp16 (single-term P * H) ----------------
// CTA 128j x 128c. 8 warps (wm 0..3)x(wn 0..1) -> 32j x 64c. K chunks of 32,
// double-buffered cp.async. Fragments via ldmatrix.x4.
#define TSTRIDE 40
#define TILE_BF (128 * TSTRIDE)       // 5120 halfs per array
#define STAGE_BF (2 * TILE_BF)        // P, H
#define PV_SMEM (2 * STAGE_BF * 2)    // 40960 B

extern __shared__ __half pv_sm[];

__device__ __forceinline__ void pv_load_stage(
    __half* st, const __half* H16, int j0, int c0, int kc, int tid) {
    const u32 sb = smem_u32(st);
#pragma unroll
    for (int r = 0; r < 2; r++) {                 // A: 128 rows x 4 chunks (P)
        int e = tid + 256 * r;
        int row = e >> 2, c16 = e & 3;
        const size_t src = (size_t)(j0 + row) * NN + kc + c16 * 8;
        cp16(sb + row * (TSTRIDE * 2) + c16 * 16, &d_P16[src]);
    }
#pragma unroll
    for (int r = 0; r < 2; r++) {                 // B: 128 rows x 4 chunks (H16)
        int e = tid + 256 * r;
        int row = e >> 2, c16 = e & 3;
        const size_t src = (size_t)(c0 + row) * NN + kc + c16 * 8;
        cp16(sb + TILE_BF * 2 + row * (TSTRIDE * 2) + c16 * 16, &H16[src]);
    }
    CP_COMMIT();
}

__global__ void __launch_bounds__(256, 2) pv_kernel(
    int b, const float* __restrict__ x, const float* __restrict__ gamma,
    float* __restrict__ out) {
    const int j0 = blockIdx.x * 128;
    const int c0 = blockIdx.y * 128;
    const int tid = threadIdx.x;
    const int lane = tid & 31, wid = tid >> 5;
    const int g = lane >> 2, t4 = lane & 3;
    const int jw = (wid >> 1) * 32;               // warp j offset
    const int cw = (wid & 1) * 64;                // warp c offset

    const __half* H16 = d_hT16 + (size_t)b * CC * NN;

    // per-lane ldmatrix offsets (bytes within one array tile)
    const int rowA = lane & 15, khalf = lane >> 4;        // A: x4 = a0..a3
    u32 offA[2];
#pragma unroll
    for (int mi = 0; mi < 2; mi++)
        offA[mi] = (u32)((jw + mi * 16 + rowA) * (TSTRIDE * 2) + khalf * 16);
    const int grp = lane >> 3, row8 = lane & 7;           // B: x4 = {b0,b1} x 2 ni
    u32 offB[4];
#pragma unroll
    for (int p = 0; p < 4; p++)
        offB[p] = (u32)((cw + (2 * p + (grp >> 1)) * 8 + row8) * (TSTRIDE * 2) + (grp & 1) * 16);

    float acc[2][8][4];
#pragma unroll
    for (int mi = 0; mi < 2; mi++)
#pragma unroll
        for (int ni = 0; ni < 8; ni++)
#pragma unroll
            for (int q = 0; q < 4; q++) acc[mi][ni][q] = 0.f;

    pv_load_stage(pv_sm, H16, j0, c0, 0, tid);

    const u32 smb = smem_u32(pv_sm);
    for (int tch = 0; tch < 128; tch++) {
        if (tch + 1 < 128) {
            pv_load_stage(pv_sm + ((tch + 1) & 1) * STAGE_BF, H16,
                          j0, c0, (tch + 1) * 32, tid);
            CP_WAIT(1);
        } else {
            CP_WAIT(0);
        }
        __syncthreads();

        const u32 stb = smb + (u32)((tch & 1) * STAGE_BF * 2);
        const u32 bA  = stb;
        const u32 bB  = stb + TILE_BF * 2;

#pragma unroll
        for (int s = 0; s < 2; s++) {
            const u32 sOff = s * 32;              // 16 halfs = 32 B
            u32 a[2][4];
#pragma unroll
            for (int mi = 0; mi < 2; mi++)
                ldsm_x4(a[mi], bA + offA[mi] + sOff);
#pragma unroll
            for (int p = 0; p < 4; p++) {
                u32 bh[4];
                ldsm_x4(bh, bB + offB[p] + sOff);
#pragma unroll
                for (int mi = 0; mi < 2; mi++) {
                    mma_f16(acc[mi][2 * p],     a[mi], bh[0], bh[1]);
                    mma_f16(acc[mi][2 * p + 1], a[mi], bh[2], bh[3]);
                }
            }
        }
        __syncthreads();
    }

    // epilogue: y[b,c,j] = gamma * o + x
    const float gam = gamma[0];
    const size_t xb = (size_t)b * CC * NN;
#pragma unroll
    for (int mi = 0; mi < 2; mi++) {
        const int m0 = j0 + jw + mi * 16 + g;
#pragma unroll
        for (int ni = 0; ni < 8; ni++) {
            const int n0 = c0 + cw + ni * 8 + 2 * t4;
            const size_t i00 = xb + (size_t)n0 * NN + m0;
            const size_t i01 = i00 + NN;
            out[i00]     = gam * acc[mi][ni][0] + x[i00];
            out[i01]     = gam * acc[mi][ni][1] + x[i01];
            out[i00 + 8] = gam * acc[mi][ni][2] + x[i00 + 8];
            out[i01 + 8] = gam * acc[mi][ni][3] + x[i01 + 8];
        }
    }
}

// ---------------- launch ----------------
extern "C" void kernel_launch(void* const* d_in, const int* in_sizes, int n_in,
                              void* d_out, int out_size) {
    (void)in_sizes; (void)n_in; (void)out_size;
    const float* x     = (const float*)d_in[0];
    const float* Wf    = (const float*)d_in[1];
    const float* bf    = (const float*)d_in[2];
    const float* Wg    = (const float*)d_in[3];
    const float* bg    = (const float*)d_in[4];
    const float* Wh    = (const float*)d_in[5];
    const float* bh    = (const float*)d_in[6];
    const float* gamma = (const float*)d_in[7];
    const float* uf    = (const float*)d_in[8];
    const float* ug    = (const float*)d_in[9];
    const float* uh    = (const float*)d_in[10];
    float* out = (float*)d_out;

    cudaFuncSetAttribute(s_kernel, cudaFuncAttributeMaxDynamicSharedMemorySize, S_SMEM);
    cudaFuncSetAttribute(pv_kernel, cudaFuncAttributeMaxDynamicSharedMemorySize, PV_SMEM);

    sigma_kernel<<<3, 512>>>(Wf, Wg, Wh, uf, ug, uh);
    proj_kernel<<<dim3(NN / 64, 10, BB), dim3(16, 16)>>>(x, Wf, bf, Wg, bg, Wh, bh);
    for (int b = 0; b < BB; b++) {
        s_kernel<<<dim3(NN / 128, NN / 128), 256, S_SMEM>>>(b);
        softmax_kernel<<<NN, 256>>>();
        pv_kernel<<<dim3(NN / 128, CC / 128), 256, PV_SMEM>>>(b, x, gamma, out);
    }
}

// round 17
// speedup vs baseline: 2.7193x; 1.4948x over previous
#include <cuda_runtime.h>
#include <cuda_fp16.h>
#include <math.h>
#include <stdint.h>

#define BB 8
#define CC 512
#define CQ 64
#define NN 4096   // H*W
#define MM 640    // concat output rows: f(64) + g(64) + h(512)

typedef unsigned long long u64;
typedef unsigned int u32;

// ---------------- packed helpers ----------------
__device__ __forceinline__ u64 pack2(float lo, float hi) {
    u64 r; asm("mov.b64 %0, {%1, %2};" : "=l"(r) : "f"(lo), "f"(hi)); return r;
}
__device__ __forceinline__ u32 f16x2(float lo, float hi) {
    u32 r; asm("cvt.rn.f16x2.f32 %0, %1, %2;" : "=r"(r) : "f"(hi), "f"(lo)); return r;
}

// ---------------- cp.async / smem helpers ----------------
__device__ __forceinline__ u32 smem_u32(const void* p) {
    u32 a;
    asm("{ .reg .u64 t; cvta.to.shared.u64 t, %1; cvt.u32.u64 %0, t; }" : "=r"(a) : "l"(p));
    return a;
}
__device__ __forceinline__ void cp16(u32 s, const void* g) {
    asm volatile("cp.async.cg.shared.global [%0], [%1], 16;" :: "r"(s), "l"(g));
}
#define CP_COMMIT()  asm volatile("cp.async.commit_group;" ::: "memory")
#define CP_WAIT(n)   asm volatile("cp.async.wait_group %0;" :: "n"(n) : "memory")

// ---------------- warp mma.sync fp16 + ldmatrix ----------------
__device__ __forceinline__ void mma_f16(float* c, const u32* a, u32 b0, u32 b1) {
    asm volatile(
        "mma.sync.aligned.m16n8k16.row.col.f32.f16.f16.f32 "
        "{%0,%1,%2,%3}, {%4,%5,%6,%7}, {%8,%9}, {%0,%1,%2,%3};"
        : "+f"(c[0]), "+f"(c[1]), "+f"(c[2]), "+f"(c[3])
        : "r"(a[0]), "r"(a[1]), "r"(a[2]), "r"(a[3]), "r"(b0), "r"(b1));
}
__device__ __forceinline__ void ldsm_x4(u32* r, u32 addr) {
    asm volatile("ldmatrix.sync.aligned.m8n8.x4.shared.b16 {%0,%1,%2,%3}, [%4];"
                 : "=r"(r[0]), "=r"(r[1]), "=r"(r[2]), "=r"(r[3]) : "r"(addr));
}
__device__ __forceinline__ void ldsm_x4_t(u32* r, u32 addr) {
    asm volatile("ldmatrix.sync.aligned.m8n8.x4.trans.shared.b16 {%0,%1,%2,%3}, [%4];"
                 : "=r"(r[0]), "=r"(r[1]), "=r"(r[2]), "=r"(r[3]) : "r"(addr));
}

// ---------------- scratch (~146 MB) ----------------
__device__ __half d_f16[(size_t)BB * NN * CQ];            // f (b,i,d)  4 MB
__device__ __half d_g16[(size_t)BB * NN * CQ];            // g (b,j,d)  4 MB
__device__ __half d_hT16[(size_t)BB * CC * NN];           // hT (b,c,i) 8 MB
__device__ float d_S[(size_t)NN * NN];                    // S (1 batch) 64 MB
__device__ __half d_P16[(size_t)NN * NN];                 // P fp16     32 MB
__device__ __half d_x16[(size_t)BB * CC * NN];            // x fp16     32 MB
__device__ __half d_W16[(size_t)MM * CC];                 // Wcat/sigma 0.64 MB
__device__ float d_bcat[MM];
__device__ float d_t[3][CC];
__device__ float d_tpart[3][8][CC];                       // deterministic partials
__device__ float d_spart[3][8];

// ---------------- 1) sigma pipeline (wide, deterministic: no atomics) ----------------
// partial t = W^T u over 64-row chunks -> d_tpart[w][chunk][c]
__global__ void sig_k1(const float* __restrict__ Wf, const float* __restrict__ Wg,
                       const float* __restrict__ Wh, const float* __restrict__ uf,
                       const float* __restrict__ ug, const float* __restrict__ uh) {
    const int w = blockIdx.x, chunk = blockIdx.y;
    const float* W; const float* u; int M;
    if (w == 0)      { W = Wf; u = uf; M = CQ; }
    else if (w == 1) { W = Wg; u = ug; M = CQ; }
    else             { W = Wh; u = uh; M = CC; }
    const int m0 = chunk * 64;
    const int tid = threadIdx.x;   // 512
    float acc = 0.f;
    if (m0 < M) {
#pragma unroll 8
        for (int m = m0; m < m0 + 64; m++) acc += W[(size_t)m * CC + tid] * u[m];
    }
    d_tpart[w][chunk][tid] = acc;
}

// sum partials (fixed order), normalize t -> v
__global__ void sig_k2() {
    const int w = blockIdx.x;
    const int tid = threadIdx.x;   // 512
    __shared__ float red[512];
    float v = 0.f;
#pragma unroll
    for (int c = 0; c < 8; c++) v += d_tpart[w][c][tid];
    red[tid] = v * v;
    __syncthreads();
    for (int s = 256; s > 0; s >>= 1) { if (tid < s) red[tid] += red[tid + s]; __syncthreads(); }
    const float inv = 1.f / (sqrtf(red[0]) + 1e-12f);
    d_t[w][tid] = v * inv;
}

// partial ||W v||^2 over 64-row chunks -> d_spart[w][chunk]
__global__ void sig_k3(const float* __restrict__ Wf, const float* __restrict__ Wg,
                       const float* __restrict__ Wh) {
    const int w = blockIdx.x, chunk = blockIdx.y;
    const float* W;
    int M;
    if (w == 0)      { W = Wf; M = CQ; }
    else if (w == 1) { W = Wg; M = CQ; }
    else             { W = Wh; M = CC; }
    const int m0 = chunk * 64;
    const int tid = threadIdx.x;   // 256
    const int lane = tid & 31, warp = tid >> 5;
    __shared__ float wsum[8];
    float local = 0.f;
    if (m0 < M) {
#pragma unroll
        for (int r = 0; r < 8; r++) {
            const int m = m0 + warp * 8 + r;
            const float* Wr = W + (size_t)m * CC;
            float a = 0.f;
#pragma unroll 4
            for (int k = lane; k < CC; k += 32) a += Wr[k] * d_t[w][k];
#pragma unroll
            for (int o = 16; o > 0; o >>= 1) a += __shfl_xor_sync(0xFFFFFFFFu, a, o);
            local += a * a;
        }
    }
    if (lane == 0) wsum[warp] = local;
    __syncthreads();
    if (tid == 0) {
        float s = 0.f;
#pragma unroll
        for (int i = 0; i < 8; i++) s += wsum[i];
        d_spart[w][chunk] = s;
    }
}

// ---------------- 2a) convert W (scaled by 1/sigma) + bias concat ----------------
__global__ void wconv(const float* __restrict__ Wf, const float* __restrict__ bf,
                      const float* __restrict__ Wg, const float* __restrict__ bg,
                      const float* __restrict__ Wh, const float* __restrict__ bh) {
    const int m = blockIdx.x;       // 0..639
    const int tid = threadIdx.x;    // 256
    const float* W; const float* bias; int seg, row;
    if (m < 64)       { seg = 0; W = Wf; bias = bf; row = m; }
    else if (m < 128) { seg = 1; W = Wg; bias = bg; row = m - 64; }
    else              { seg = 2; W = Wh; bias = bh; row = m - 128; }
    float nw2 = 0.f;
#pragma unroll
    for (int c = 0; c < 8; c++) nw2 += d_spart[seg][c];   // fixed-order sum
    const float nw = sqrtf(nw2);
    const float rs = (nw + 1e-12f) / nw2;    // 1/sigma
#pragma unroll
    for (int r = 0; r < 2; r++) {
        const int c = tid + 256 * r;
        d_W16[(size_t)m * CC + c] = __float2half_rn(W[(size_t)row * CC + c] * rs);
    }
    if (tid == 0) d_bcat[m] = bias[row];
}

// ---------------- 2b) convert x -> fp16 ----------------
__global__ void xconv(const float* __restrict__ x) {
    const size_t i = ((size_t)blockIdx.x * 256 + threadIdx.x) * 4;
    float4 v = *(const float4*)&x[i];
    uint2 p; p.x = f16x2(v.x, v.y); p.y = f16x2(v.z, v.w);
    *(uint2*)&d_x16[i] = p;
}

// ---------------- 2c) proj GEMM via mma: [f;g;h] = W16 @ x16 + b ----------------
// CTA 128m x 128n. 8 warps (wm 0..3)x(wn 0..1) -> 32m x 64n. K=512, chunks of 32.
#define PAST 40                         // A row stride (halfs)
#define PBST 136                        // B row stride (halfs)
#define PA_TILE (128 * PAST)            // 5120 halfs
#define PB_TILE (32 * PBST)             // 4352 halfs
#define PSTAGE (PA_TILE + PB_TILE)      // 9472 halfs
#define PJ_SMEM (2 * PSTAGE * 2)        // 37888 B

extern __shared__ __half pj_sm[];

__device__ __forceinline__ void pj_load_stage(
    __half* st, int m0, int n0, int b, int kc, int tid) {
    const u32 sb = smem_u32(st);
#pragma unroll
    for (int r = 0; r < 2; r++) {                 // A: W16 128 rows x 4 chunks
        int e = tid + 256 * r;
        int row = e >> 2, c16 = e & 3;
        cp16(sb + row * (PAST * 2) + c16 * 16,
             &d_W16[(size_t)(m0 + row) * CC + kc + c16 * 8]);
    }
#pragma unroll
    for (int r = 0; r < 2; r++) {                 // B: x16 32 rows x 16 chunks
        int e = tid + 256 * r;
        int row = e >> 4, c16 = e & 15;
        cp16(sb + PA_TILE * 2 + row * (PBST * 2) + c16 * 16,
             &d_x16[((size_t)b * CC + kc + row) * NN + n0 + c16 * 8]);
    }
    CP_COMMIT();
}

__global__ void __launch_bounds__(256, 2) proj_mma(void) {
    const int n0 = blockIdx.x * 128;
    const int m0 = blockIdx.y * 128;
    const int b  = blockIdx.z;
    const int tid = threadIdx.x;
    const int lane = tid & 31, wid = tid >> 5;
    const int g = lane >> 2, t4 = lane & 3;
    const int mw = (wid >> 1) * 32;               // warp m offset
    const int nw = (wid & 1) * 64;                // warp n offset

    __shared__ float bs[128];
    if (tid < 128) bs[tid] = d_bcat[m0 + tid];

    // A ldmatrix offsets (regular): row = m, 16B half-k
    const int rowA = lane & 15, khalf = lane >> 4;
    u32 offA[2];
#pragma unroll
    for (int mi = 0; mi < 2; mi++)
        offA[mi] = (u32)((mw + mi * 16 + rowA) * (PAST * 2) + khalf * 16);
    // B ldmatrix.trans offsets on [k][n] memory
    const int grp = lane >> 3, row8 = lane & 7;
    u32 offB[4];
#pragma unroll
    for (int p = 0; p < 4; p++)
        offB[p] = (u32)(((grp & 1) * 8 + row8) * (PBST * 2)
                        + (nw + p * 16 + (grp >> 1) * 8) * 2);

    float acc[2][8][4];
#pragma unroll
    for (int mi = 0; mi < 2; mi++)
#pragma unroll
        for (int ni = 0; ni < 8; ni++)
#pragma unroll
            for (int q = 0; q < 4; q++) acc[mi][ni][q] = 0.f;

    pj_load_stage(pj_sm, m0, n0, b, 0, tid);

    const u32 smb = smem_u32(pj_sm);
    for (int tch = 0; tch < 16; tch++) {
        if (tch + 1 < 16) {
            pj_load_stage(pj_sm + ((tch + 1) & 1) * PSTAGE, m0, n0, b, (tch + 1) * 32, tid);
            CP_WAIT(1);
        } else {
            CP_WAIT(0);
        }
        __syncthreads();

        const u32 stb = smb + (u32)((tch & 1) * PSTAGE * 2);
        const u32 bA  = stb;
        const u32 bB  = stb + PA_TILE * 2;

#pragma unroll
        for (int s = 0; s < 2; s++) {
            u32 a[2][4];
#pragma unroll
            for (int mi = 0; mi < 2; mi++)
                ldsm_x4(a[mi], bA + offA[mi] + s * 32);
#pragma unroll
            for (int p = 0; p < 4; p++) {
                u32 bb[4];
                ldsm_x4_t(bb, bB + offB[p] + s * 16 * (PBST * 2));
#pragma unroll
                for (int mi = 0; mi < 2; mi++) {
                    mma_f16(acc[mi][2 * p],     a[mi], bb[0], bb[1]);
                    mma_f16(acc[mi][2 * p + 1], a[mi], bb[2], bb[3]);
                }
            }
        }
        __syncthreads();
    }

    // epilogue: add bias; route rows to f/g/h
#pragma unroll
    for (int mi = 0; mi < 2; mi++) {
        const int ml0 = mw + mi * 16 + g;          // local m, +8 for q2/q3
#pragma unroll
        for (int ni = 0; ni < 8; ni++) {
            const int n = n0 + nw + ni * 8 + 2 * t4;
            const float v0 = acc[mi][ni][0] + bs[ml0];
            const float v1 = acc[mi][ni][1] + bs[ml0];
            const float v2 = acc[mi][ni][2] + bs[ml0 + 8];
            const float v3 = acc[mi][ni][3] + bs[ml0 + 8];
            const int mg0 = m0 + ml0;
            const int mg1 = mg0 + 8;
            if (m0 == 0 && ml0 < 128) {            // f/g rows (only m-tile 0)
                __half* D0 = (mg0 < 64) ? d_f16 : d_g16;
                __half* D1 = (mg1 < 64) ? d_f16 : d_g16;
                const int r0 = (mg0 < 64) ? mg0 : mg0 - 64;
                const int r1 = (mg1 < 64) ? mg1 : mg1 - 64;
                D0[((size_t)b * NN + n) * CQ + r0]     = __float2half_rn(v0);
                D0[((size_t)b * NN + n + 1) * CQ + r0] = __float2half_rn(v1);
                D1[((size_t)b * NN + n) * CQ + r1]     = __float2half_rn(v2);
                D1[((size_t)b * NN + n + 1) * CQ + r1] = __float2half_rn(v3);
            } else {                                // h rows
                *(u32*)&d_hT16[((size_t)b * CC + mg0 - 128) * NN + n] = f16x2(v0, v1);
                *(u32*)&d_hT16[((size_t)b * CC + mg1 - 128) * NN + n] = f16x2(v2, v3);
            }
        }
    }
}

// ---------------- 3) S = g f^T via single-term fp16 mma ----------------
#define SST 72
#define S_TILE (128 * SST)
#define S_SMEM (2 * S_TILE * 2)

extern __shared__ __half s_sm[];

__global__ void __launch_bounds__(256, 2) s_kernel(int b) {
    const int j0 = blockIdx.x * 128;
    const int i0 = blockIdx.y * 128;
    const int tid = threadIdx.x;
    const int lane = tid & 31, wid = tid >> 5;
    const int g = lane >> 2, t4 = lane & 3;
    const int jw = (wid >> 1) * 32;
    const int iw = (wid & 1) * 64;

    __half* sg = s_sm;
    __half* sf = s_sm + S_TILE;

    {
        const u32 sb = smem_u32(s_sm);
#pragma unroll
        for (int r = 0; r < 4; r++) {
            int e = tid + 256 * r;
            int row = e >> 3, c16 = e & 7;
            u32 doff = row * (SST * 2) + c16 * 16;
            const size_t gsrc = ((size_t)b * NN + j0 + row) * CQ + c16 * 8;
            const size_t fsrc = ((size_t)b * NN + i0 + row) * CQ + c16 * 8;
            cp16(sb + doff, &d_g16[gsrc]);
            cp16(sb + S_TILE * 2 + doff, &d_f16[fsrc]);
        }
        CP_COMMIT();
        CP_WAIT(0);
    }
    __syncthreads();

    float acc[2][8][4];
#pragma unroll
    for (int mi = 0; mi < 2; mi++)
#pragma unroll
        for (int ni = 0; ni < 8; ni++)
#pragma unroll
            for (int q = 0; q < 4; q++) acc[mi][ni][q] = 0.f;

#pragma unroll
    for (int ks = 0; ks < 4; ks++) {
        const int cA = ks * 16 + 2 * t4;
        u32 a[2][4];
#pragma unroll
        for (int mi = 0; mi < 2; mi++) {
            const int r0 = jw + mi * 16 + g;
            a[mi][0] = *(const u32*)&sg[r0 * SST + cA];
            a[mi][1] = *(const u32*)&sg[(r0 + 8) * SST + cA];
            a[mi][2] = *(const u32*)&sg[r0 * SST + cA + 8];
            a[mi][3] = *(const u32*)&sg[(r0 + 8) * SST + cA + 8];
        }
#pragma unroll
        for (int ni = 0; ni < 8; ni++) {
            const int nr = iw + ni * 8 + g;
            u32 b0 = *(const u32*)&sf[nr * SST + cA];
            u32 b1 = *(const u32*)&sf[nr * SST + cA + 8];
#pragma unroll
            for (int mi = 0; mi < 2; mi++)
                mma_f16(acc[mi][ni], a[mi], b0, b1);
        }
    }

#pragma unroll
    for (int mi = 0; mi < 2; mi++) {
        const int m0 = j0 + jw + mi * 16 + g;
#pragma unroll
        for (int ni = 0; ni < 8; ni++) {
            const int ic = i0 + iw + ni * 8 + 2 * t4;
            *(u64*)&d_S[(size_t)m0 * NN + ic] = pack2(acc[mi][ni][0], acc[mi][ni][1]);
            *(u64*)&d_S[(size_t)(m0 + 8) * NN + ic] = pack2(acc[mi][ni][2], acc[mi][ni][3]);
        }
    }
}

// ---------------- 4) row softmax over i; emit P as fp16 ----------------
__global__ void __launch_bounds__(256) softmax_kernel() {
    const int j = blockIdx.x;
    const float* row = d_S + (size_t)j * NN;
    const int tid = threadIdx.x;
    const int lane = tid & 31, warp = tid >> 5;
    __shared__ float red[8];
    __shared__ float bcast;

    float4 v[4];
#pragma unroll
    for (int r = 0; r < 4; r++) v[r] = *(const float4*)&row[(tid + 256 * r) * 4];

    float m = -INFINITY;
#pragma unroll
    for (int r = 0; r < 4; r++)
        m = fmaxf(m, fmaxf(fmaxf(v[r].x, v[r].y), fmaxf(v[r].z, v[r].w)));
#pragma unroll
    for (int o = 16; o > 0; o >>= 1) m = fmaxf(m, __shfl_xor_sync(0xFFFFFFFFu, m, o));
    if (lane == 0) red[warp] = m;
    __syncthreads();
    if (tid == 0) {
        float mm = red[0];
#pragma unroll
        for (int i = 1; i < 8; i++) mm = fmaxf(mm, red[i]);
        bcast = mm;
    }
    __syncthreads();
    const float M = bcast;

    float s = 0.f;
#pragma unroll
    for (int r = 0; r < 4; r++) {
        v[r].x = __expf(v[r].x - M); v[r].y = __expf(v[r].y - M);
        v[r].z = __expf(v[r].z - M); v[r].w = __expf(v[r].w - M);
        s += v[r].x + v[r].y + v[r].z + v[r].w;
    }
#pragma unroll
    for (int o = 16; o > 0; o >>= 1) s += __shfl_xor_sync(0xFFFFFFFFu, s, o);
    if (lane == 0) red[warp] = s;
    __syncthreads();
    if (tid == 0) {
        float ss = 0.f;
#pragma unroll
        for (int i = 0; i < 8; i++) ss += red[i];
        bcast = 1.f / ss;
    }
    __syncthreads();
    const float inv = bcast;
    const size_t ro = (size_t)j * NN;
#pragma unroll
    for (int r = 0; r < 4; r++) {
        uint2 p;
        p.x = f16x2(v[r].x * inv, v[r].y * inv);
        p.y = f16x2(v[r].z * inv, v[r].w * inv);
        const size_t idx = ro + (size_t)(tid + 256 * r) * 4;
        *(uint2*)&d_P16[idx] = p;
    }
}

// ---------------- 5) PV via mma.sync fp16 (single-term P * H) ----------------
#define TSTRIDE 40
#define TILE_BF (128 * TSTRIDE)
#define STAGE_BF (2 * TILE_BF)
#define PV_SMEM (2 * STAGE_BF * 2)

extern __shared__ __half pv_sm[];

__device__ __forceinline__ void pv_load_stage(
    __half* st, const __half* H16, int j0, int c0, int kc, int tid) {
    const u32 sb = smem_u32(st);
#pragma unroll
    for (int r = 0; r < 2; r++) {
        int e = tid + 256 * r;
        int row = e >> 2, c16 = e & 3;
        cp16(sb + row * (TSTRIDE * 2) + c16 * 16,
             &d_P16[(size_t)(j0 + row) * NN + kc + c16 * 8]);
    }
#pragma unroll
    for (int r = 0; r < 2; r++) {
        int e = tid + 256 * r;
        int row = e >> 2, c16 = e & 3;
        cp16(sb + TILE_BF * 2 + row * (TSTRIDE * 2) + c16 * 16,
             &H16[(size_t)(c0 + row) * NN + kc + c16 * 8]);
    }
    CP_COMMIT();
}

__global__ void __launch_bounds__(256, 2) pv_kernel(
    int b, const float* __restrict__ x, const float* __restrict__ gamma,
    float* __restrict__ out) {
    const int j0 = blockIdx.x * 128;
    const int c0 = blockIdx.y * 128;
    const int tid = threadIdx.x;
    const int lane = tid & 31, wid = tid >> 5;
    const int g = lane >> 2, t4 = lane & 3;
    const int jw = (wid >> 1) * 32;
    const int cw = (wid & 1) * 64;

    const __half* H16 = d_hT16 + (size_t)b * CC * NN;

    const int rowA = lane & 15, khalf = lane >> 4;
    u32 offA[2];
#pragma unroll
    for (int mi = 0; mi < 2; mi++)
        offA[mi] = (u32)((jw + mi * 16 + rowA) * (TSTRIDE * 2) + khalf * 16);
    const int grp = lane >> 3, row8 = lane & 7;
    u32 offB[4];
#pragma unroll
    for (int p = 0; p < 4; p++)
        offB[p] = (u32)((cw + (2 * p + (grp >> 1)) * 8 + row8) * (TSTRIDE * 2) + (grp & 1) * 16);

    float acc[2][8][4];
#pragma unroll
    for (int mi = 0; mi < 2; mi++)
#pragma unroll
        for (int ni = 0; ni < 8; ni++)
#pragma unroll
            for (int q = 0; q < 4; q++) acc[mi][ni][q] = 0.f;

    pv_load_stage(pv_sm, H16, j0, c0, 0, tid);

    const u32 smb = smem_u32(pv_sm);
    for (int tch = 0; tch < 128; tch++) {
        if (tch + 1 < 128) {
            pv_load_stage(pv_sm + ((tch + 1) & 1) * STAGE_BF, H16,
                          j0, c0, (tch + 1) * 32, tid);
            CP_WAIT(1);
        } else {
            CP_WAIT(0);
        }
        __syncthreads();

        const u32 stb = smb + (u32)((tch & 1) * STAGE_BF * 2);
        const u32 bA  = stb;
        const u32 bB  = stb + TILE_BF * 2;

#pragma unroll
        for (int s = 0; s < 2; s++) {
            const u32 sOff = s * 32;
            u32 a[2][4];
#pragma unroll
            for (int mi = 0; mi < 2; mi++)
                ldsm_x4(a[mi], bA + offA[mi] + sOff);
#pragma unroll
            for (int p = 0; p < 4; p++) {
                u32 bh[4];
                ldsm_x4(bh, bB + offB[p] + sOff);
#pragma unroll
                for (int mi = 0; mi < 2; mi++) {
                    mma_f16(acc[mi][2 * p],     a[mi], bh[0], bh[1]);
                    mma_f16(acc[mi][2 * p + 1], a[mi], bh[2], bh[3]);
                }
            }
        }
        __syncthreads();
    }

    const float gam = gamma[0];
    const size_t xb = (size_t)b * CC * NN;
#pragma unroll
    for (int mi = 0; mi < 2; mi++) {
        const int m0 = j0 + jw + mi * 16 + g;
#pragma unroll
        for (int ni = 0; ni < 8; ni++) {
            const int n0 = c0 + cw + ni * 8 + 2 * t4;
            const size_t i00 = xb + (size_t)n0 * NN + m0;
            const size_t i01 = i00 + NN;
            out[i00]     = gam * acc[mi][ni][0] + x[i00];
            out[i01]     = gam * acc[mi][ni][1] + x[i01];
            out[i00 + 8] = gam * acc[mi][ni][2] + x[i00 + 8];
            out[i01 + 8] = gam * acc[mi][ni][3] + x[i01 + 8];
        }
    }
}

// ---------------- launch ----------------
extern "C" void kernel_launch(void* const* d_in, const int* in_sizes, int n_in,
                              void* d_out, int out_size) {
    (void)in_sizes; (void)n_in; (void)out_size;
    const float* x     = (const float*)d_in[0];
    const float* Wf    = (const float*)d_in[1];
    const float* bf    = (const float*)d_in[2];
    const float* Wg    = (const float*)d_in[3];
    const float* bg    = (const float*)d_in[4];
    const float* Wh    = (const float*)d_in[5];
    const float* bh    = (const float*)d_in[6];
    const float* gamma = (const float*)d_in[7];
    const float* uf    = (const float*)d_in[8];
    const float* ug    = (const float*)d_in[9];
    const float* uh    = (const float*)d_in[10];
    float* out = (float*)d_out;

    cudaFuncSetAttribute(proj_mma, cudaFuncAttributeMaxDynamicSharedMemorySize, PJ_SMEM);
    cudaFuncSetAttribute(s_kernel, cudaFuncAttributeMaxDynamicSharedMemorySize, S_SMEM);
    cudaFuncSetAttribute(pv_kernel, cudaFuncAttributeMaxDynamicSharedMemorySize, PV_SMEM);

    sig_k1<<<dim3(3, 8), 512>>>(Wf, Wg, Wh, uf, ug, uh);
    sig_k2<<<3, 512>>>();
    sig_k3<<<dim3(3, 8), 256>>>(Wf, Wg, Wh);
    wconv<<<MM, 256>>>(Wf, bf, Wg, bg, Wh, bh);
    xconv<<<(int)(((size_t)BB * CC * NN) / 1024), 256>>>(x);
    proj_mma<<<dim3(NN / 128, MM / 128, BB), 256, PJ_SMEM>>>();
    for (int b = 0; b < BB; b++) {
        s_kernel<<<dim3(NN / 128, NN / 128), 256, S_SMEM>>>(b);
        softmax_kernel<<<NN, 256>>>();
        pv_kernel<<<dim3(NN / 128, CC / 128), 256, PV_SMEM>>>(b, x, gamma, out);
    }
}